// round 1
// baseline (speedup 1.0000x reference)
#include <cuda_runtime.h>
#include <math.h>

#define BN   2
#define NPTS 8192
#define KNN  16
#define CIN  32
#define EIN  67      // 32 + 32 + 3
#define HID  128
#define COUT 64
#define TOT  (BN*NPTS)

// Scratch (no allocations allowed)
__device__ int    g_idx[TOT*KNN];
__device__ float  g_mid[TOT*COUT];
__device__ float4 g_vert4[TOT];

// ---------------------------------------------------------------------------
// Prep: pack vertices as (x,y,z,|v|^2) for 1-LDG.128 candidate streaming
// ---------------------------------------------------------------------------
__global__ void prep_kernel(const float* __restrict__ verts) {
    int i = blockIdx.x * blockDim.x + threadIdx.x;
    if (i < TOT) {
        float x = verts[i*3+0], y = verts[i*3+1], z = verts[i*3+2];
        g_vert4[i] = make_float4(x, y, z, x*x + y*y + z*z);
    }
}

// ---------------------------------------------------------------------------
// KNN: one thread per query, full scan with register-resident top-16
// (replace-max scheme). Output is an unordered neighbor set; order is
// irrelevant because downstream reduces with a mean over K.
// ---------------------------------------------------------------------------
__global__ void __launch_bounds__(128) knn_kernel() {
    int b = blockIdx.y;
    int q = blockIdx.x * blockDim.x + threadIdx.x;
    int base = b * NPTS;

    float4 qv = g_vert4[base + q];
    float qx = qv.x, qy = qv.y, qz = qv.z, qsq = qv.w;

    float bd[KNN];
    int   bi[KNN];
#pragma unroll
    for (int s = 0; s < KNN; s++) { bd[s] = 3.4e38f; bi[s] = 0; }
    float worst = 3.4e38f;

    for (int j = 0; j < NPTS; j++) {
        float4 c = __ldg(&g_vert4[base + j]);
        float dot = qx*c.x + qy*c.y + qz*c.z;
        float d = qsq + c.w - 2.0f*dot;
        if (d < worst) {
            int slot = 0; float mv = bd[0];
#pragma unroll
            for (int s = 1; s < KNN; s++) if (bd[s] > mv) { mv = bd[s]; slot = s; }
#pragma unroll
            for (int s = 0; s < KNN; s++) if (s == slot) { bd[s] = d; bi[s] = j; }
            worst = bd[0];
#pragma unroll
            for (int s = 1; s < KNN; s++) worst = fmaxf(worst, bd[s]);
        }
    }
#pragma unroll
    for (int s = 0; s < KNN; s++) g_idx[(base+q)*KNN + s] = bi[s];
}

// ---------------------------------------------------------------------------
// GELU, exact match of jax.nn.gelu(approximate=True)
// ---------------------------------------------------------------------------
__device__ __forceinline__ float gelu_tanh(float x) {
    float inner = 0.7978845608028654f * fmaf(0.044715f * x * x, x, x);
    return 0.5f * x * (1.0f + tanhf(inner));
}

// ---------------------------------------------------------------------------
// MLP1 fused: per block = 8 points (128 edges).
//   X[128,67] @ W1[67,128] + b1 -> LN -> GELU -> @ W2[128,64], mean over K,
//   + b2 -> g_mid
// 256 threads (16x16), stage1 thread tile 8x8, stage2 8x4.
// ---------------------------------------------------------------------------
__global__ void __launch_bounds__(256, 1) mlp1_kernel(
    const float* __restrict__ verts, const float* __restrict__ feat,
    const float* __restrict__ W1,  const float* __restrict__ b1,
    const float* __restrict__ g1,  const float* __restrict__ be1,
    const float* __restrict__ W2,  const float* __restrict__ b2)
{
    extern __shared__ float sm[];
    float* sXt = sm;                    // [EIN][128]   transposed edge features
    float* sW1 = sXt + EIN*128;         // [EIN][128]
    float* sH  = sW1 + EIN*128;         // [128][132]   hidden (padded)
    float* sW2 = sH  + 128*132;         // [128][64]
    __shared__ int snb[128];

    int tid = threadIdx.x;
    int gp0 = blockIdx.x * 8;
    int b   = gp0 / NPTS;
    int p0  = gp0 % NPTS;
    int bN  = b * NPTS;

    if (tid < 128)
        snb[tid] = g_idx[(bN + p0 + (tid >> 4))*KNN + (tid & 15)];
    for (int e = tid; e < EIN*HID;  e += 256) sW1[e] = W1[e];
    for (int e = tid; e < HID*COUT; e += 256) sW2[e] = W2[e];
    __syncthreads();

    // Build transposed edge matrix: sXt[k][r]
    for (int e = tid; e < EIN*128; e += 256) {
        int k = e >> 7, r = e & 127;
        int p  = p0 + (r >> 4);
        int nb = snb[r];
        float v;
        if (k < CIN)          v = feat[(bN + nb)*CIN + k];
        else if (k < 2*CIN)   v = feat[(bN + p)*CIN + (k - CIN)];
        else                  v = verts[(bN + nb)*3 + (k - 2*CIN)]
                                - verts[(bN + p )*3 + (k - 2*CIN)];
        sXt[k*128 + r] = v;
    }
    __syncthreads();

    int tx = tid & 15, ty = tid >> 4;

    // ---- Stage 1: H = X @ W1 ----
    float acc[8][8];
#pragma unroll
    for (int i = 0; i < 8; i++)
#pragma unroll
        for (int j = 0; j < 8; j++) acc[i][j] = 0.f;

    for (int k = 0; k < EIN; k++) {
        float4 a0 = *(const float4*)&sXt[k*128 + ty*8];
        float4 a1 = *(const float4*)&sXt[k*128 + ty*8 + 4];
        float4 c0 = *(const float4*)&sW1[k*128 + tx*8];
        float4 c1 = *(const float4*)&sW1[k*128 + tx*8 + 4];
        float a[8] = {a0.x,a0.y,a0.z,a0.w,a1.x,a1.y,a1.z,a1.w};
        float w[8] = {c0.x,c0.y,c0.z,c0.w,c1.x,c1.y,c1.z,c1.w};
#pragma unroll
        for (int i = 0; i < 8; i++)
#pragma unroll
            for (int j = 0; j < 8; j++)
                acc[i][j] = fmaf(a[i], w[j], acc[i][j]);
    }

    // ---- bias + LayerNorm + GELU, write sH (row-major, stride 132) ----
    float b1j[8], gj[8], bej[8];
#pragma unroll
    for (int j = 0; j < 8; j++) {
        int col = tx*8 + j;
        b1j[j] = b1[col]; gj[j] = g1[col]; bej[j] = be1[col];
    }
#pragma unroll
    for (int i = 0; i < 8; i++) {
        float ps = 0.f, ps2 = 0.f;
#pragma unroll
        for (int j = 0; j < 8; j++) {
            float h = acc[i][j] + b1j[j];
            acc[i][j] = h;
            ps += h; ps2 = fmaf(h, h, ps2);
        }
#pragma unroll
        for (int off = 8; off; off >>= 1) {
            ps  += __shfl_xor_sync(0xffffffffu, ps,  off);
            ps2 += __shfl_xor_sync(0xffffffffu, ps2, off);
        }
        float mu  = ps  * (1.f/HID);
        float var = ps2 * (1.f/HID) - mu*mu;
        float rs  = rsqrtf(var + 1e-5f);
        float o[8];
#pragma unroll
        for (int j = 0; j < 8; j++) {
            float xn = (acc[i][j] - mu) * rs * gj[j] + bej[j];
            o[j] = gelu_tanh(xn);
        }
        int row = ty*8 + i;
        *(float4*)&sH[row*132 + tx*8]     = make_float4(o[0],o[1],o[2],o[3]);
        *(float4*)&sH[row*132 + tx*8 + 4] = make_float4(o[4],o[5],o[6],o[7]);
    }
    __syncthreads();

    // ---- Stage 2: Y = G @ W2, mean over 16 edges per point ----
    float acc2[8][4];
#pragma unroll
    for (int i = 0; i < 8; i++)
#pragma unroll
        for (int j = 0; j < 4; j++) acc2[i][j] = 0.f;

    for (int k = 0; k < HID; k++) {
        float4 wv = *(const float4*)&sW2[k*COUT + tx*4];
        float a[8];
#pragma unroll
        for (int i = 0; i < 8; i++) a[i] = sH[(ty*8+i)*132 + k];
#pragma unroll
        for (int i = 0; i < 8; i++) {
            acc2[i][0] = fmaf(a[i], wv.x, acc2[i][0]);
            acc2[i][1] = fmaf(a[i], wv.y, acc2[i][1]);
            acc2[i][2] = fmaf(a[i], wv.z, acc2[i][2]);
            acc2[i][3] = fmaf(a[i], wv.w, acc2[i][3]);
        }
    }

    // rows ty*8..ty*8+7 all belong to point group g = ty/2 (16 rows/point)
#pragma unroll
    for (int j = 0; j < 4; j++) {
        float s = 0.f;
#pragma unroll
        for (int i = 0; i < 8; i++) s += acc2[i][j];
        s += __shfl_xor_sync(0xffffffffu, s, 16);
        if ((ty & 1) == 0) {
            int p   = p0 + (ty >> 1);
            int col = tx*4 + j;
            g_mid[(bN + p)*COUT + col] = s * (1.f/KNN) + b2[col];
        }
    }
}

// ---------------------------------------------------------------------------
// MLP2 fused: per block = 128 points.
//   mid[128,64] @ Wo1[64,128] + bo1 -> LN -> GELU -> @ Wo2[128,64] + bo2 -> out
// ---------------------------------------------------------------------------
__global__ void __launch_bounds__(256, 1) mlp2_kernel(
    const float* __restrict__ Wo1, const float* __restrict__ bo1,
    const float* __restrict__ go,  const float* __restrict__ beo,
    const float* __restrict__ Wo2, const float* __restrict__ bo2,
    float* __restrict__ out)
{
    extern __shared__ float sm[];
    float* sAt  = sm;                  // [64][128] transposed mid
    float* sWo1 = sAt  + 64*128;       // [64][128]
    float* sH   = sWo1 + 64*128;       // [128][132]
    float* sWo2 = sH   + 128*132;      // [128][64]

    int tid = threadIdx.x;
    int r0  = blockIdx.x * 128;

    for (int e = tid; e < COUT*HID; e += 256) sWo1[e] = Wo1[e];
    for (int e = tid; e < HID*COUT; e += 256) sWo2[e] = Wo2[e];
    for (int e = tid; e < COUT*128; e += 256) {
        int k = e >> 7, r = e & 127;
        sAt[k*128 + r] = g_mid[(r0 + r)*COUT + k];
    }
    __syncthreads();

    int tx = tid & 15, ty = tid >> 4;

    float acc[8][8];
#pragma unroll
    for (int i = 0; i < 8; i++)
#pragma unroll
        for (int j = 0; j < 8; j++) acc[i][j] = 0.f;

    for (int k = 0; k < COUT; k++) {
        float4 a0 = *(const float4*)&sAt[k*128 + ty*8];
        float4 a1 = *(const float4*)&sAt[k*128 + ty*8 + 4];
        float4 c0 = *(const float4*)&sWo1[k*128 + tx*8];
        float4 c1 = *(const float4*)&sWo1[k*128 + tx*8 + 4];
        float a[8] = {a0.x,a0.y,a0.z,a0.w,a1.x,a1.y,a1.z,a1.w};
        float w[8] = {c0.x,c0.y,c0.z,c0.w,c1.x,c1.y,c1.z,c1.w};
#pragma unroll
        for (int i = 0; i < 8; i++)
#pragma unroll
            for (int j = 0; j < 8; j++)
                acc[i][j] = fmaf(a[i], w[j], acc[i][j]);
    }

    float b1j[8], gj[8], bej[8];
#pragma unroll
    for (int j = 0; j < 8; j++) {
        int col = tx*8 + j;
        b1j[j] = bo1[col]; gj[j] = go[col]; bej[j] = beo[col];
    }
#pragma unroll
    for (int i = 0; i < 8; i++) {
        float ps = 0.f, ps2 = 0.f;
#pragma unroll
        for (int j = 0; j < 8; j++) {
            float h = acc[i][j] + b1j[j];
            acc[i][j] = h;
            ps += h; ps2 = fmaf(h, h, ps2);
        }
#pragma unroll
        for (int off = 8; off; off >>= 1) {
            ps  += __shfl_xor_sync(0xffffffffu, ps,  off);
            ps2 += __shfl_xor_sync(0xffffffffu, ps2, off);
        }
        float mu  = ps  * (1.f/HID);
        float var = ps2 * (1.f/HID) - mu*mu;
        float rs  = rsqrtf(var + 1e-5f);
        float o[8];
#pragma unroll
        for (int j = 0; j < 8; j++) {
            float xn = (acc[i][j] - mu) * rs * gj[j] + bej[j];
            o[j] = gelu_tanh(xn);
        }
        int row = ty*8 + i;
        *(float4*)&sH[row*132 + tx*8]     = make_float4(o[0],o[1],o[2],o[3]);
        *(float4*)&sH[row*132 + tx*8 + 4] = make_float4(o[4],o[5],o[6],o[7]);
    }
    __syncthreads();

    float acc2[8][4];
#pragma unroll
    for (int i = 0; i < 8; i++)
#pragma unroll
        for (int j = 0; j < 4; j++) acc2[i][j] = 0.f;

    for (int k = 0; k < HID; k++) {
        float4 wv = *(const float4*)&sWo2[k*COUT + tx*4];
        float a[8];
#pragma unroll
        for (int i = 0; i < 8; i++) a[i] = sH[(ty*8+i)*132 + k];
#pragma unroll
        for (int i = 0; i < 8; i++) {
            acc2[i][0] = fmaf(a[i], wv.x, acc2[i][0]);
            acc2[i][1] = fmaf(a[i], wv.y, acc2[i][1]);
            acc2[i][2] = fmaf(a[i], wv.z, acc2[i][2]);
            acc2[i][3] = fmaf(a[i], wv.w, acc2[i][3]);
        }
    }

    float b2j[4];
#pragma unroll
    for (int j = 0; j < 4; j++) b2j[j] = bo2[tx*4 + j];
#pragma unroll
    for (int i = 0; i < 8; i++) {
        int row = r0 + ty*8 + i;
#pragma unroll
        for (int j = 0; j < 4; j++)
            out[row*COUT + tx*4 + j] = acc2[i][j] + b2j[j];
    }
}

// ---------------------------------------------------------------------------
extern "C" void kernel_launch(void* const* d_in, const int* in_sizes, int n_in,
                              void* d_out, int out_size) {
    const float* verts = (const float*)d_in[0];
    const float* feat  = (const float*)d_in[1];
    const float* W1    = (const float*)d_in[2];
    const float* b1    = (const float*)d_in[3];
    const float* g1    = (const float*)d_in[4];
    const float* be1   = (const float*)d_in[5];
    const float* W2    = (const float*)d_in[6];
    const float* b2    = (const float*)d_in[7];
    const float* Wo1   = (const float*)d_in[8];
    const float* bo1   = (const float*)d_in[9];
    const float* go    = (const float*)d_in[10];
    const float* beo   = (const float*)d_in[11];
    const float* Wo2   = (const float*)d_in[12];
    const float* bo2   = (const float*)d_in[13];
    float* out = (float*)d_out;

    const int smem1 = (EIN*128 + EIN*128 + 128*132 + 128*64) * 4;   // 168960
    const int smem2 = (64*128 + 64*128 + 128*132 + 128*64) * 4;     // 165888
    cudaFuncSetAttribute(mlp1_kernel, cudaFuncAttributeMaxDynamicSharedMemorySize, smem1);
    cudaFuncSetAttribute(mlp2_kernel, cudaFuncAttributeMaxDynamicSharedMemorySize, smem2);

    prep_kernel<<<(TOT + 255)/256, 256>>>(verts);
    knn_kernel<<<dim3(NPTS/128, BN), 128>>>();
    mlp1_kernel<<<TOT/8, 256, smem1>>>(verts, feat, W1, b1, g1, be1, W2, b2);
    mlp2_kernel<<<TOT/128, 256, smem2>>>(Wo1, bo1, go, beo, Wo2, bo2, out);
}

// round 2
// speedup vs baseline: 1.7516x; 1.7516x over previous
#include <cuda_runtime.h>
#include <math.h>

#define BN   2
#define NPTS 8192
#define KNN  16
#define CIN  32
#define EIN  67      // 32 + 32 + 3
#define HID  128
#define COUT 64
#define TOT  (BN*NPTS)
#define CH   8
#define CLEN (NPTS/CH)   // 1024

// Scratch (no allocations allowed)
__device__ int    g_idx[TOT*KNN];
__device__ float  g_mid[TOT*COUT];
__device__ float4 g_vert4[TOT];
__device__ float  g_pd[TOT*CH*KNN];
__device__ int    g_pi[TOT*CH*KNN];

// ---------------------------------------------------------------------------
// Prep: pack vertices as (x,y,z,|v|^2)
// ---------------------------------------------------------------------------
__global__ void prep_kernel(const float* __restrict__ verts) {
    int i = blockIdx.x * blockDim.x + threadIdx.x;
    if (i < TOT) {
        float x = verts[i*3+0], y = verts[i*3+1], z = verts[i*3+2];
        g_vert4[i] = make_float4(x, y, z, x*x + y*y + z*z);
    }
}

// ---------------------------------------------------------------------------
// KNN phase A: candidate-split. Thread = (query, chunk). Scans CLEN
// candidates keeping a register top-16 (replace-max). All threads in a block
// share the same candidate stream -> broadcast L1-resident loads.
// ---------------------------------------------------------------------------
__global__ void __launch_bounds__(128) knn_part_kernel() {
    int b = blockIdx.z;
    int c = blockIdx.y;
    int q = blockIdx.x * 128 + threadIdx.x;
    int base = b * NPTS;

    float4 qv = g_vert4[base + q];
    float qx = qv.x, qy = qv.y, qz = qv.z, qsq = qv.w;

    float bd[KNN];
    int   bi[KNN];
#pragma unroll
    for (int s = 0; s < KNN; s++) { bd[s] = 3.4e38f; bi[s] = 0; }
    float worst = 3.4e38f;

    int j0 = c * CLEN;
#pragma unroll 4
    for (int jj = 0; jj < CLEN; jj++) {
        int j = j0 + jj;
        float4 cd = __ldg(&g_vert4[base + j]);
        float dot = qx*cd.x + qy*cd.y + qz*cd.z;
        float d = qsq + cd.w - 2.0f*dot;
        if (d < worst) {
            int slot = 0; float mv = bd[0];
#pragma unroll
            for (int s = 1; s < KNN; s++) if (bd[s] > mv) { mv = bd[s]; slot = s; }
#pragma unroll
            for (int s = 0; s < KNN; s++) if (s == slot) { bd[s] = d; bi[s] = j; }
            worst = bd[0];
#pragma unroll
            for (int s = 1; s < KNN; s++) worst = fmaxf(worst, bd[s]);
        }
    }
    int o = ((base + q)*CH + c)*KNN;
#pragma unroll
    for (int s = 0; s < KNN; s++) { g_pd[o+s] = bd[s]; g_pi[o+s] = bi[s]; }
}

// ---------------------------------------------------------------------------
// KNN phase B: merge the CH partial top-16 lists per query.
// ---------------------------------------------------------------------------
__global__ void __launch_bounds__(256) knn_merge_kernel() {
    int t = blockIdx.x * blockDim.x + threadIdx.x;
    if (t >= TOT) return;

    float bd[KNN];
    int   bi[KNN];
#pragma unroll
    for (int s = 0; s < KNN; s++) { bd[s] = 3.4e38f; bi[s] = 0; }
    float worst = 3.4e38f;

    int o = t*CH*KNN;
    for (int e = 0; e < CH*KNN; e++) {
        float d = g_pd[o+e];
        if (d < worst) {
            int slot = 0; float mv = bd[0];
#pragma unroll
            for (int s = 1; s < KNN; s++) if (bd[s] > mv) { mv = bd[s]; slot = s; }
            int id = g_pi[o+e];
#pragma unroll
            for (int s = 0; s < KNN; s++) if (s == slot) { bd[s] = d; bi[s] = id; }
            worst = bd[0];
#pragma unroll
            for (int s = 1; s < KNN; s++) worst = fmaxf(worst, bd[s]);
        }
    }
#pragma unroll
    for (int s = 0; s < KNN; s++) g_idx[t*KNN + s] = bi[s];
}

// ---------------------------------------------------------------------------
__device__ __forceinline__ float gelu_tanh(float x) {
    float inner = 0.7978845608028654f * fmaf(0.044715f * x * x, x, x);
    return 0.5f * x * (1.0f + tanhf(inner));
}

// ---------------------------------------------------------------------------
// MLP1 fused: block = 8 points (128 edges). Shared-memory ALIASED:
// sH (stage-2 input) reuses the sXt/sW1 region after stage 1, cutting smem
// from 169KB to 101KB -> 2 blocks/SM.
// ---------------------------------------------------------------------------
#define R1REG (EIN*128)          // 8576 floats per matrix
#define SMEM1_FLOATS (2*R1REG + HID*COUT)   // 17152 + 8192 = 25344

__global__ void __launch_bounds__(256, 2) mlp1_kernel(
    const float* __restrict__ verts, const float* __restrict__ feat,
    const float* __restrict__ W1,  const float* __restrict__ b1,
    const float* __restrict__ g1,  const float* __restrict__ be1,
    const float* __restrict__ W2,  const float* __restrict__ b2)
{
    extern __shared__ float sm[];
    float* sXt = sm;                    // [EIN][128]
    float* sW1 = sm + R1REG;            // [EIN][128]
    float* sH  = sm;                    // [128][132] ALIASES sXt/sW1 (16896 <= 17152)
    float* sW2 = sm + 2*R1REG;          // [128][64]
    __shared__ int snb[128];

    int tid = threadIdx.x;
    int gp0 = blockIdx.x * 8;
    int b   = gp0 / NPTS;
    int p0  = gp0 % NPTS;
    int bN  = b * NPTS;

    if (tid < 128)
        snb[tid] = g_idx[(bN + p0 + (tid >> 4))*KNN + (tid & 15)];
    for (int e = tid; e < EIN*HID;  e += 256) sW1[e] = W1[e];
    for (int e = tid; e < HID*COUT; e += 256) sW2[e] = W2[e];
    __syncthreads();

    // Build transposed edge matrix sXt[k][r]
    for (int e = tid; e < EIN*128; e += 256) {
        int k = e >> 7, r = e & 127;
        int p  = p0 + (r >> 4);
        int nb = snb[r];
        float v;
        if (k < CIN)          v = feat[(bN + nb)*CIN + k];
        else if (k < 2*CIN)   v = feat[(bN + p)*CIN + (k - CIN)];
        else                  v = verts[(bN + nb)*3 + (k - 2*CIN)]
                                - verts[(bN + p )*3 + (k - 2*CIN)];
        sXt[k*128 + r] = v;
    }
    __syncthreads();

    int tx = tid & 15, ty = tid >> 4;

    // ---- Stage 1: H = X @ W1 (8x8 per thread) ----
    float acc[8][8];
#pragma unroll
    for (int i = 0; i < 8; i++)
#pragma unroll
        for (int j = 0; j < 8; j++) acc[i][j] = 0.f;

    for (int k = 0; k < EIN; k++) {
        float4 a0 = *(const float4*)&sXt[k*128 + ty*8];
        float4 a1 = *(const float4*)&sXt[k*128 + ty*8 + 4];
        float4 c0 = *(const float4*)&sW1[k*128 + tx*8];
        float4 c1 = *(const float4*)&sW1[k*128 + tx*8 + 4];
        float a[8] = {a0.x,a0.y,a0.z,a0.w,a1.x,a1.y,a1.z,a1.w};
        float w[8] = {c0.x,c0.y,c0.z,c0.w,c1.x,c1.y,c1.z,c1.w};
#pragma unroll
        for (int i = 0; i < 8; i++)
#pragma unroll
            for (int j = 0; j < 8; j++)
                acc[i][j] = fmaf(a[i], w[j], acc[i][j]);
    }

    __syncthreads();   // all reads of sXt/sW1 done before sH overwrites them

    // ---- bias + LayerNorm + GELU -> sH (row-major, stride 132) ----
    float b1j[8], gj[8], bej[8];
#pragma unroll
    for (int j = 0; j < 8; j++) {
        int col = tx*8 + j;
        b1j[j] = b1[col]; gj[j] = g1[col]; bej[j] = be1[col];
    }
#pragma unroll
    for (int i = 0; i < 8; i++) {
        float ps = 0.f, ps2 = 0.f;
#pragma unroll
        for (int j = 0; j < 8; j++) {
            float h = acc[i][j] + b1j[j];
            acc[i][j] = h;
            ps += h; ps2 = fmaf(h, h, ps2);
        }
#pragma unroll
        for (int off = 8; off; off >>= 1) {
            ps  += __shfl_xor_sync(0xffffffffu, ps,  off);
            ps2 += __shfl_xor_sync(0xffffffffu, ps2, off);
        }
        float mu  = ps  * (1.f/HID);
        float var = ps2 * (1.f/HID) - mu*mu;
        float rs  = rsqrtf(var + 1e-5f);
        float o[8];
#pragma unroll
        for (int j = 0; j < 8; j++) {
            float xn = (acc[i][j] - mu) * rs * gj[j] + bej[j];
            o[j] = gelu_tanh(xn);
        }
        int row = ty*8 + i;
        *(float4*)&sH[row*132 + tx*8]     = make_float4(o[0],o[1],o[2],o[3]);
        *(float4*)&sH[row*132 + tx*8 + 4] = make_float4(o[4],o[5],o[6],o[7]);
    }
    __syncthreads();

    // ---- Stage 2: Y = H @ W2, k-unrolled x4 with float4 H loads ----
    float acc2[8][4];
#pragma unroll
    for (int i = 0; i < 8; i++)
#pragma unroll
        for (int j = 0; j < 4; j++) acc2[i][j] = 0.f;

    for (int k = 0; k < HID; k += 4) {
        float4 w0 = *(const float4*)&sW2[(k+0)*COUT + tx*4];
        float4 w1 = *(const float4*)&sW2[(k+1)*COUT + tx*4];
        float4 w2 = *(const float4*)&sW2[(k+2)*COUT + tx*4];
        float4 w3 = *(const float4*)&sW2[(k+3)*COUT + tx*4];
#pragma unroll
        for (int i = 0; i < 8; i++) {
            float4 av = *(const float4*)&sH[(ty*8+i)*132 + k];
            acc2[i][0] = fmaf(av.x, w0.x, fmaf(av.y, w1.x, fmaf(av.z, w2.x, fmaf(av.w, w3.x, acc2[i][0]))));
            acc2[i][1] = fmaf(av.x, w0.y, fmaf(av.y, w1.y, fmaf(av.z, w2.y, fmaf(av.w, w3.y, acc2[i][1]))));
            acc2[i][2] = fmaf(av.x, w0.z, fmaf(av.y, w1.z, fmaf(av.z, w2.z, fmaf(av.w, w3.z, acc2[i][2]))));
            acc2[i][3] = fmaf(av.x, w0.w, fmaf(av.y, w1.w, fmaf(av.z, w2.w, fmaf(av.w, w3.w, acc2[i][3]))));
        }
    }

    // mean over 16 edges per point (rows ty*8..ty*8+7 belong to point ty/2)
#pragma unroll
    for (int j = 0; j < 4; j++) {
        float s = 0.f;
#pragma unroll
        for (int i = 0; i < 8; i++) s += acc2[i][j];
        s += __shfl_xor_sync(0xffffffffu, s, 16);
        if ((ty & 1) == 0) {
            int p   = p0 + (ty >> 1);
            int col = tx*4 + j;
            g_mid[(bN + p)*COUT + col] = s * (1.f/KNN) + b2[col];
        }
    }
}

// ---------------------------------------------------------------------------
// MLP2 fused: block = 128 points. Same aliasing trick.
//   region1 = sAt(8192) + sWo1(8192) = 16384 ; sH(16896) aliases+overflows a
//   bit, so sW2 sits at offset 16896.
// ---------------------------------------------------------------------------
#define SMEM2_FLOATS (HID*132 + HID*COUT)   // 16896 + 8192 = 25088

__global__ void __launch_bounds__(256, 2) mlp2_kernel(
    const float* __restrict__ Wo1, const float* __restrict__ bo1,
    const float* __restrict__ go,  const float* __restrict__ beo,
    const float* __restrict__ Wo2, const float* __restrict__ bo2,
    float* __restrict__ out)
{
    extern __shared__ float sm[];
    float* sAt  = sm;                  // [64][128]
    float* sWo1 = sm + 64*128;         // [64][128]
    float* sH   = sm;                  // [128][132] aliases (needs 16896 <= region+pad)
    float* sWo2 = sm + HID*132;        // [128][64]

    int tid = threadIdx.x;
    int r0  = blockIdx.x * 128;

    for (int e = tid; e < COUT*HID; e += 256) sWo1[e] = Wo1[e];
    for (int e = tid; e < HID*COUT; e += 256) sWo2[e] = Wo2[e];
    for (int e = tid; e < COUT*128; e += 256) {
        int k = e >> 7, r = e & 127;
        sAt[k*128 + r] = g_mid[(r0 + r)*COUT + k];
    }
    __syncthreads();

    int tx = tid & 15, ty = tid >> 4;

    float acc[8][8];
#pragma unroll
    for (int i = 0; i < 8; i++)
#pragma unroll
        for (int j = 0; j < 8; j++) acc[i][j] = 0.f;

    for (int k = 0; k < COUT; k++) {
        float4 a0 = *(const float4*)&sAt[k*128 + ty*8];
        float4 a1 = *(const float4*)&sAt[k*128 + ty*8 + 4];
        float4 c0 = *(const float4*)&sWo1[k*128 + tx*8];
        float4 c1 = *(const float4*)&sWo1[k*128 + tx*8 + 4];
        float a[8] = {a0.x,a0.y,a0.z,a0.w,a1.x,a1.y,a1.z,a1.w};
        float w[8] = {c0.x,c0.y,c0.z,c0.w,c1.x,c1.y,c1.z,c1.w};
#pragma unroll
        for (int i = 0; i < 8; i++)
#pragma unroll
            for (int j = 0; j < 8; j++)
                acc[i][j] = fmaf(a[i], w[j], acc[i][j]);
    }

    __syncthreads();   // reads of sAt/sWo1 done before sH overwrite

    float b1j[8], gj[8], bej[8];
#pragma unroll
    for (int j = 0; j < 8; j++) {
        int col = tx*8 + j;
        b1j[j] = bo1[col]; gj[j] = go[col]; bej[j] = beo[col];
    }
#pragma unroll
    for (int i = 0; i < 8; i++) {
        float ps = 0.f, ps2 = 0.f;
#pragma unroll
        for (int j = 0; j < 8; j++) {
            float h = acc[i][j] + b1j[j];
            acc[i][j] = h;
            ps += h; ps2 = fmaf(h, h, ps2);
        }
#pragma unroll
        for (int off = 8; off; off >>= 1) {
            ps  += __shfl_xor_sync(0xffffffffu, ps,  off);
            ps2 += __shfl_xor_sync(0xffffffffu, ps2, off);
        }
        float mu  = ps  * (1.f/HID);
        float var = ps2 * (1.f/HID) - mu*mu;
        float rs  = rsqrtf(var + 1e-5f);
        float o[8];
#pragma unroll
        for (int j = 0; j < 8; j++) {
            float xn = (acc[i][j] - mu) * rs * gj[j] + bej[j];
            o[j] = gelu_tanh(xn);
        }
        int row = ty*8 + i;
        *(float4*)&sH[row*132 + tx*8]     = make_float4(o[0],o[1],o[2],o[3]);
        *(float4*)&sH[row*132 + tx*8 + 4] = make_float4(o[4],o[5],o[6],o[7]);
    }
    __syncthreads();

    float acc2[8][4];
#pragma unroll
    for (int i = 0; i < 8; i++)
#pragma unroll
        for (int j = 0; j < 4; j++) acc2[i][j] = 0.f;

    for (int k = 0; k < HID; k += 4) {
        float4 w0 = *(const float4*)&sWo2[(k+0)*COUT + tx*4];
        float4 w1 = *(const float4*)&sWo2[(k+1)*COUT + tx*4];
        float4 w2 = *(const float4*)&sWo2[(k+2)*COUT + tx*4];
        float4 w3 = *(const float4*)&sWo2[(k+3)*COUT + tx*4];
#pragma unroll
        for (int i = 0; i < 8; i++) {
            float4 av = *(const float4*)&sH[(ty*8+i)*132 + k];
            acc2[i][0] = fmaf(av.x, w0.x, fmaf(av.y, w1.x, fmaf(av.z, w2.x, fmaf(av.w, w3.x, acc2[i][0]))));
            acc2[i][1] = fmaf(av.x, w0.y, fmaf(av.y, w1.y, fmaf(av.z, w2.y, fmaf(av.w, w3.y, acc2[i][1]))));
            acc2[i][2] = fmaf(av.x, w0.z, fmaf(av.y, w1.z, fmaf(av.z, w2.z, fmaf(av.w, w3.z, acc2[i][2]))));
            acc2[i][3] = fmaf(av.x, w0.w, fmaf(av.y, w1.w, fmaf(av.z, w2.w, fmaf(av.w, w3.w, acc2[i][3]))));
        }
    }

    float b2j[4];
#pragma unroll
    for (int j = 0; j < 4; j++) b2j[j] = bo2[tx*4 + j];
#pragma unroll
    for (int i = 0; i < 8; i++) {
        int row = r0 + ty*8 + i;
#pragma unroll
        for (int j = 0; j < 4; j++)
            out[row*COUT + tx*4 + j] = acc2[i][j] + b2j[j];
    }
}

// ---------------------------------------------------------------------------
extern "C" void kernel_launch(void* const* d_in, const int* in_sizes, int n_in,
                              void* d_out, int out_size) {
    const float* verts = (const float*)d_in[0];
    const float* feat  = (const float*)d_in[1];
    const float* W1    = (const float*)d_in[2];
    const float* b1    = (const float*)d_in[3];
    const float* g1    = (const float*)d_in[4];
    const float* be1   = (const float*)d_in[5];
    const float* W2    = (const float*)d_in[6];
    const float* b2    = (const float*)d_in[7];
    const float* Wo1   = (const float*)d_in[8];
    const float* bo1   = (const float*)d_in[9];
    const float* go    = (const float*)d_in[10];
    const float* beo   = (const float*)d_in[11];
    const float* Wo2   = (const float*)d_in[12];
    const float* bo2   = (const float*)d_in[13];
    float* out = (float*)d_out;

    const int smem1 = SMEM1_FLOATS * 4;   // 101376
    const int smem2 = SMEM2_FLOATS * 4;   // 100352
    cudaFuncSetAttribute(mlp1_kernel, cudaFuncAttributeMaxDynamicSharedMemorySize, smem1);
    cudaFuncSetAttribute(mlp2_kernel, cudaFuncAttributeMaxDynamicSharedMemorySize, smem2);

    prep_kernel<<<(TOT + 255)/256, 256>>>(verts);
    knn_part_kernel<<<dim3(NPTS/128, CH, BN), 128>>>();
    knn_merge_kernel<<<(TOT + 255)/256, 256>>>();
    mlp1_kernel<<<TOT/8, 256, smem1>>>(verts, feat, W1, b1, g1, be1, W2, b2);
    mlp2_kernel<<<TOT/128, 256, smem2>>>(Wo1, bo1, go, beo, Wo2, bo2, out);
}

// round 3
// speedup vs baseline: 4.0701x; 2.3237x over previous
#include <cuda_runtime.h>
#include <math.h>

#define BN   2
#define NPTS 8192
#define KNN  16
#define CIN  32
#define EIN  67      // 32 + 32 + 3
#define HID  128
#define COUT 64
#define TOT  (BN*NPTS)

// Scratch (no allocations allowed)
__device__ int    g_idx[TOT*KNN];
__device__ float  g_mid[TOT*COUT];
__device__ float4 g_vert4[TOT];

// ---------------------------------------------------------------------------
// Prep: pack vertices as (x,y,z,|v|^2)
// ---------------------------------------------------------------------------
__global__ void prep_kernel(const float* __restrict__ verts) {
    int i = blockIdx.x * blockDim.x + threadIdx.x;
    if (i < TOT) {
        float x = verts[i*3+0], y = verts[i*3+1], z = verts[i*3+2];
        g_vert4[i] = make_float4(x, y, z, x*x + y*y + z*z);
    }
}

// ---------------------------------------------------------------------------
// KNN: one WARP per query. The warp's 32 lanes hold the best-32-so-far in
// ascending order (lane 0 = nearest). Candidates are filtered against the
// 16th-best (lane 15); passing candidates are inserted with a 2-shuffle
// sorted-shift. Event probability ~ min(1, 16/batch) -> ~60 events and
// ~120 inserts per query over 256 batches.
// ---------------------------------------------------------------------------
__global__ void __launch_bounds__(256) knn_kernel() {
    const unsigned FULL = 0xffffffffu;
    int gwarp = (blockIdx.x * 256 + threadIdx.x) >> 5;   // 0..TOT-1
    int lane  = threadIdx.x & 31;
    int b     = gwarp >> 13;          // / NPTS
    int qi    = gwarp & (NPTS - 1);
    int base  = b * NPTS;

    float4 qv = g_vert4[base + qi];
    float qx = qv.x, qy = qv.y, qz = qv.z, qsq = qv.w;

    // sorted warp queue
    float key = 3.4e38f;
    int   idx = 0;
    float thresh = 3.4e38f;

#pragma unroll 2
    for (int i = 0; i < NPTS/32; i++) {
        int j = i*32 + lane;
        float4 c = g_vert4[base + j];
        float dot = fmaf(qx, c.x, fmaf(qy, c.y, qz*c.z));
        float d   = fmaf(-2.0f, dot, qsq + c.w);
        unsigned mask = __ballot_sync(FULL, d < thresh);
        if (mask) {
            do {
                int src = __ffs(mask) - 1;
                mask &= mask - 1;
                float v  = __shfl_sync(FULL, d, src);
                int   vi = i*32 + src;
                if (v < thresh) {
                    // insert (v,vi) into ascending lane-sorted queue
                    float pk = __shfl_up_sync(FULL, key, 1);
                    int   pi = __shfl_up_sync(FULL, idx, 1);
                    bool gt  = (v < key);
                    bool gtp = (lane > 0) && (v < pk);
                    if (gt) {
                        if (gtp) { key = pk; idx = pi; }
                        else     { key = v;  idx = vi; }
                    }
                    thresh = __shfl_sync(FULL, key, 15);
                }
            } while (mask);
        }
    }

    if (lane < KNN) g_idx[(base + qi)*KNN + lane] = idx;
}

// ---------------------------------------------------------------------------
__device__ __forceinline__ float gelu_tanh(float x) {
    float inner = 0.7978845608028654f * fmaf(0.044715f * x * x, x, x);
    return 0.5f * x * (1.0f + tanhf(inner));
}

// ---------------------------------------------------------------------------
// MLP1 fused: block = 8 points (128 edges). smem aliased: sH reuses sXt/sW1
// after stage 1 -> 101KB -> 2 blocks/SM. (At fp32 FFMA roofline.)
// ---------------------------------------------------------------------------
#define R1REG (EIN*128)                      // 8576 floats per matrix
#define SMEM1_FLOATS (2*R1REG + HID*COUT)    // 25344

__global__ void __launch_bounds__(256, 2) mlp1_kernel(
    const float* __restrict__ verts, const float* __restrict__ feat,
    const float* __restrict__ W1,  const float* __restrict__ b1,
    const float* __restrict__ g1,  const float* __restrict__ be1,
    const float* __restrict__ W2,  const float* __restrict__ b2)
{
    extern __shared__ float sm[];
    float* sXt = sm;                    // [EIN][128]
    float* sW1 = sm + R1REG;            // [EIN][128]
    float* sH  = sm;                    // [128][132] ALIASES sXt/sW1
    float* sW2 = sm + 2*R1REG;          // [128][64]
    __shared__ int snb[128];

    int tid = threadIdx.x;
    int gp0 = blockIdx.x * 8;
    int b   = gp0 / NPTS;
    int p0  = gp0 % NPTS;
    int bN  = b * NPTS;

    if (tid < 128)
        snb[tid] = g_idx[(bN + p0 + (tid >> 4))*KNN + (tid & 15)];
    for (int e = tid; e < EIN*HID;  e += 256) sW1[e] = W1[e];
    for (int e = tid; e < HID*COUT; e += 256) sW2[e] = W2[e];
    __syncthreads();

    for (int e = tid; e < EIN*128; e += 256) {
        int k = e >> 7, r = e & 127;
        int p  = p0 + (r >> 4);
        int nb = snb[r];
        float v;
        if (k < CIN)          v = feat[(bN + nb)*CIN + k];
        else if (k < 2*CIN)   v = feat[(bN + p)*CIN + (k - CIN)];
        else                  v = verts[(bN + nb)*3 + (k - 2*CIN)]
                                - verts[(bN + p )*3 + (k - 2*CIN)];
        sXt[k*128 + r] = v;
    }
    __syncthreads();

    int tx = tid & 15, ty = tid >> 4;

    float acc[8][8];
#pragma unroll
    for (int i = 0; i < 8; i++)
#pragma unroll
        for (int j = 0; j < 8; j++) acc[i][j] = 0.f;

    for (int k = 0; k < EIN; k++) {
        float4 a0 = *(const float4*)&sXt[k*128 + ty*8];
        float4 a1 = *(const float4*)&sXt[k*128 + ty*8 + 4];
        float4 c0 = *(const float4*)&sW1[k*128 + tx*8];
        float4 c1 = *(const float4*)&sW1[k*128 + tx*8 + 4];
        float a[8] = {a0.x,a0.y,a0.z,a0.w,a1.x,a1.y,a1.z,a1.w};
        float w[8] = {c0.x,c0.y,c0.z,c0.w,c1.x,c1.y,c1.z,c1.w};
#pragma unroll
        for (int i = 0; i < 8; i++)
#pragma unroll
            for (int j = 0; j < 8; j++)
                acc[i][j] = fmaf(a[i], w[j], acc[i][j]);
    }

    __syncthreads();   // all reads of sXt/sW1 done before sH overwrites

    float b1j[8], gj[8], bej[8];
#pragma unroll
    for (int j = 0; j < 8; j++) {
        int col = tx*8 + j;
        b1j[j] = b1[col]; gj[j] = g1[col]; bej[j] = be1[col];
    }
#pragma unroll
    for (int i = 0; i < 8; i++) {
        float ps = 0.f, ps2 = 0.f;
#pragma unroll
        for (int j = 0; j < 8; j++) {
            float h = acc[i][j] + b1j[j];
            acc[i][j] = h;
            ps += h; ps2 = fmaf(h, h, ps2);
        }
#pragma unroll
        for (int off = 8; off; off >>= 1) {
            ps  += __shfl_xor_sync(0xffffffffu, ps,  off);
            ps2 += __shfl_xor_sync(0xffffffffu, ps2, off);
        }
        float mu  = ps  * (1.f/HID);
        float var = ps2 * (1.f/HID) - mu*mu;
        float rs  = rsqrtf(var + 1e-5f);
        float o[8];
#pragma unroll
        for (int j = 0; j < 8; j++) {
            float xn = (acc[i][j] - mu) * rs * gj[j] + bej[j];
            o[j] = gelu_tanh(xn);
        }
        int row = ty*8 + i;
        *(float4*)&sH[row*132 + tx*8]     = make_float4(o[0],o[1],o[2],o[3]);
        *(float4*)&sH[row*132 + tx*8 + 4] = make_float4(o[4],o[5],o[6],o[7]);
    }
    __syncthreads();

    float acc2[8][4];
#pragma unroll
    for (int i = 0; i < 8; i++)
#pragma unroll
        for (int j = 0; j < 4; j++) acc2[i][j] = 0.f;

    for (int k = 0; k < HID; k += 4) {
        float4 w0 = *(const float4*)&sW2[(k+0)*COUT + tx*4];
        float4 w1 = *(const float4*)&sW2[(k+1)*COUT + tx*4];
        float4 w2 = *(const float4*)&sW2[(k+2)*COUT + tx*4];
        float4 w3 = *(const float4*)&sW2[(k+3)*COUT + tx*4];
#pragma unroll
        for (int i = 0; i < 8; i++) {
            float4 av = *(const float4*)&sH[(ty*8+i)*132 + k];
            acc2[i][0] = fmaf(av.x, w0.x, fmaf(av.y, w1.x, fmaf(av.z, w2.x, fmaf(av.w, w3.x, acc2[i][0]))));
            acc2[i][1] = fmaf(av.x, w0.y, fmaf(av.y, w1.y, fmaf(av.z, w2.y, fmaf(av.w, w3.y, acc2[i][1]))));
            acc2[i][2] = fmaf(av.x, w0.z, fmaf(av.y, w1.z, fmaf(av.z, w2.z, fmaf(av.w, w3.z, acc2[i][2]))));
            acc2[i][3] = fmaf(av.x, w0.w, fmaf(av.y, w1.w, fmaf(av.z, w2.w, fmaf(av.w, w3.w, acc2[i][3]))));
        }
    }

#pragma unroll
    for (int j = 0; j < 4; j++) {
        float s = 0.f;
#pragma unroll
        for (int i = 0; i < 8; i++) s += acc2[i][j];
        s += __shfl_xor_sync(0xffffffffu, s, 16);
        if ((ty & 1) == 0) {
            int p   = p0 + (ty >> 1);
            int col = tx*4 + j;
            g_mid[(bN + p)*COUT + col] = s * (1.f/KNN) + b2[col];
        }
    }
}

// ---------------------------------------------------------------------------
// MLP2 fused: block = 128 points, smem aliased.
// ---------------------------------------------------------------------------
#define SMEM2_FLOATS (HID*132 + HID*COUT)   // 25088

__global__ void __launch_bounds__(256, 2) mlp2_kernel(
    const float* __restrict__ Wo1, const float* __restrict__ bo1,
    const float* __restrict__ go,  const float* __restrict__ beo,
    const float* __restrict__ Wo2, const float* __restrict__ bo2,
    float* __restrict__ out)
{
    extern __shared__ float sm[];
    float* sAt  = sm;                  // [64][128]
    float* sWo1 = sm + 64*128;         // [64][128]
    float* sH   = sm;                  // [128][132] aliases
    float* sWo2 = sm + HID*132;        // [128][64]

    int tid = threadIdx.x;
    int r0  = blockIdx.x * 128;

    for (int e = tid; e < COUT*HID; e += 256) sWo1[e] = Wo1[e];
    for (int e = tid; e < HID*COUT; e += 256) sWo2[e] = Wo2[e];
    for (int e = tid; e < COUT*128; e += 256) {
        int k = e >> 7, r = e & 127;
        sAt[k*128 + r] = g_mid[(r0 + r)*COUT + k];
    }
    __syncthreads();

    int tx = tid & 15, ty = tid >> 4;

    float acc[8][8];
#pragma unroll
    for (int i = 0; i < 8; i++)
#pragma unroll
        for (int j = 0; j < 8; j++) acc[i][j] = 0.f;

    for (int k = 0; k < COUT; k++) {
        float4 a0 = *(const float4*)&sAt[k*128 + ty*8];
        float4 a1 = *(const float4*)&sAt[k*128 + ty*8 + 4];
        float4 c0 = *(const float4*)&sWo1[k*128 + tx*8];
        float4 c1 = *(const float4*)&sWo1[k*128 + tx*8 + 4];
        float a[8] = {a0.x,a0.y,a0.z,a0.w,a1.x,a1.y,a1.z,a1.w};
        float w[8] = {c0.x,c0.y,c0.z,c0.w,c1.x,c1.y,c1.z,c1.w};
#pragma unroll
        for (int i = 0; i < 8; i++)
#pragma unroll
            for (int j = 0; j < 8; j++)
                acc[i][j] = fmaf(a[i], w[j], acc[i][j]);
    }

    __syncthreads();

    float b1j[8], gj[8], bej[8];
#pragma unroll
    for (int j = 0; j < 8; j++) {
        int col = tx*8 + j;
        b1j[j] = bo1[col]; gj[j] = go[col]; bej[j] = beo[col];
    }
#pragma unroll
    for (int i = 0; i < 8; i++) {
        float ps = 0.f, ps2 = 0.f;
#pragma unroll
        for (int j = 0; j < 8; j++) {
            float h = acc[i][j] + b1j[j];
            acc[i][j] = h;
            ps += h; ps2 = fmaf(h, h, ps2);
        }
#pragma unroll
        for (int off = 8; off; off >>= 1) {
            ps  += __shfl_xor_sync(0xffffffffu, ps,  off);
            ps2 += __shfl_xor_sync(0xffffffffu, ps2, off);
        }
        float mu  = ps  * (1.f/HID);
        float var = ps2 * (1.f/HID) - mu*mu;
        float rs  = rsqrtf(var + 1e-5f);
        float o[8];
#pragma unroll
        for (int j = 0; j < 8; j++) {
            float xn = (acc[i][j] - mu) * rs * gj[j] + bej[j];
            o[j] = gelu_tanh(xn);
        }
        int row = ty*8 + i;
        *(float4*)&sH[row*132 + tx*8]     = make_float4(o[0],o[1],o[2],o[3]);
        *(float4*)&sH[row*132 + tx*8 + 4] = make_float4(o[4],o[5],o[6],o[7]);
    }
    __syncthreads();

    float acc2[8][4];
#pragma unroll
    for (int i = 0; i < 8; i++)
#pragma unroll
        for (int j = 0; j < 4; j++) acc2[i][j] = 0.f;

    for (int k = 0; k < HID; k += 4) {
        float4 w0 = *(const float4*)&sWo2[(k+0)*COUT + tx*4];
        float4 w1 = *(const float4*)&sWo2[(k+1)*COUT + tx*4];
        float4 w2 = *(const float4*)&sWo2[(k+2)*COUT + tx*4];
        float4 w3 = *(const float4*)&sWo2[(k+3)*COUT + tx*4];
#pragma unroll
        for (int i = 0; i < 8; i++) {
            float4 av = *(const float4*)&sH[(ty*8+i)*132 + k];
            acc2[i][0] = fmaf(av.x, w0.x, fmaf(av.y, w1.x, fmaf(av.z, w2.x, fmaf(av.w, w3.x, acc2[i][0]))));
            acc2[i][1] = fmaf(av.x, w0.y, fmaf(av.y, w1.y, fmaf(av.z, w2.y, fmaf(av.w, w3.y, acc2[i][1]))));
            acc2[i][2] = fmaf(av.x, w0.z, fmaf(av.y, w1.z, fmaf(av.z, w2.z, fmaf(av.w, w3.z, acc2[i][2]))));
            acc2[i][3] = fmaf(av.x, w0.w, fmaf(av.y, w1.w, fmaf(av.z, w2.w, fmaf(av.w, w3.w, acc2[i][3]))));
        }
    }

    float b2j[4];
#pragma unroll
    for (int j = 0; j < 4; j++) b2j[j] = bo2[tx*4 + j];
#pragma unroll
    for (int i = 0; i < 8; i++) {
        int row = r0 + ty*8 + i;
#pragma unroll
        for (int j = 0; j < 4; j++)
            out[row*COUT + tx*4 + j] = acc2[i][j] + b2j[j];
    }
}

// ---------------------------------------------------------------------------
extern "C" void kernel_launch(void* const* d_in, const int* in_sizes, int n_in,
                              void* d_out, int out_size) {
    const float* verts = (const float*)d_in[0];
    const float* feat  = (const float*)d_in[1];
    const float* W1    = (const float*)d_in[2];
    const float* b1    = (const float*)d_in[3];
    const float* g1    = (const float*)d_in[4];
    const float* be1   = (const float*)d_in[5];
    const float* W2    = (const float*)d_in[6];
    const float* b2    = (const float*)d_in[7];
    const float* Wo1   = (const float*)d_in[8];
    const float* bo1   = (const float*)d_in[9];
    const float* go    = (const float*)d_in[10];
    const float* beo   = (const float*)d_in[11];
    const float* Wo2   = (const float*)d_in[12];
    const float* bo2   = (const float*)d_in[13];
    float* out = (float*)d_out;

    const int smem1 = SMEM1_FLOATS * 4;   // 101376
    const int smem2 = SMEM2_FLOATS * 4;   // 100352
    cudaFuncSetAttribute(mlp1_kernel, cudaFuncAttributeMaxDynamicSharedMemorySize, smem1);
    cudaFuncSetAttribute(mlp2_kernel, cudaFuncAttributeMaxDynamicSharedMemorySize, smem2);

    prep_kernel<<<(TOT + 255)/256, 256>>>(verts);
    knn_kernel<<<TOT/8, 256>>>();                 // 8 warps/block, warp per query
    mlp1_kernel<<<TOT/8, 256, smem1>>>(verts, feat, W1, b1, g1, be1, W2, b2);
    mlp2_kernel<<<TOT/128, 256, smem2>>>(Wo1, bo1, go, beo, Wo2, bo2, out);
}

// round 4
// speedup vs baseline: 6.5207x; 1.6021x over previous
#include <cuda_runtime.h>
#include <math.h>

#define BN   2
#define NPTS 8192
#define KNN  16
#define CIN  32
#define EIN  67      // 32 + 32 + 3
#define HID  128
#define COUT 64
#define TOT  (BN*NPTS)
#define FULLM 0xffffffffu

// Scratch (no allocations allowed)
__device__ int    g_idx[TOT*KNN];          // GLOBAL neighbor indices
__device__ float  g_mid[TOT*COUT];
__device__ float4 g_vert4[TOT];
__device__ float  g_q[TOT*HID];            // Q[n] = feat@W1a + vert@W1c
__device__ float  g_p[TOT*HID];            // P[n] = feat@W1b + b1 - vert@W1c

// ---------------------------------------------------------------------------
__global__ void prep_kernel(const float* __restrict__ verts) {
    int i = blockIdx.x * blockDim.x + threadIdx.x;
    if (i < TOT) {
        float x = verts[i*3+0], y = verts[i*3+1], z = verts[i*3+2];
        g_vert4[i] = make_float4(x, y, z, x*x + y*y + z*z);
    }
}

// ---------------------------------------------------------------------------
// KNN: TWO warps per query, each scans half the candidates with an ascending
// lane-sorted best-32 queue (threshold = lane 15). Halves then merged via
// smem (sorted, so early-break on >= thresh).
// ---------------------------------------------------------------------------
__global__ void __launch_bounds__(256) knn_kernel() {
    __shared__ float sD[4][16];
    __shared__ int   sI[4][16];

    int tid  = threadIdx.x;
    int lane = tid & 31;
    int wq   = tid >> 6;          // query slot within block: 0..3
    int half = (tid >> 5) & 1;    // candidate half
    int q    = blockIdx.x * 4 + wq;
    int b    = q >> 13;
    int qi   = q & (NPTS - 1);
    int base = b * NPTS;

    float4 qv = g_vert4[base + qi];
    float qx = qv.x, qy = qv.y, qz = qv.z, qsq = qv.w;

    float key = 3.4e38f;
    int   idx = 0;
    float thresh = 3.4e38f;

    int j0 = half * (NPTS/2);
#pragma unroll 2
    for (int i = 0; i < NPTS/64; i++) {
        int j = j0 + i*32 + lane;
        float4 c = g_vert4[base + j];
        float dot = fmaf(qx, c.x, fmaf(qy, c.y, qz*c.z));
        float d   = fmaf(-2.0f, dot, qsq + c.w);
        unsigned mask = __ballot_sync(FULLM, d < thresh);
        while (mask) {
            int src = __ffs(mask) - 1;
            mask &= mask - 1;
            float v  = __shfl_sync(FULLM, d, src);
            int   vi = j0 + i*32 + src;
            if (v < thresh) {
                float pk = __shfl_up_sync(FULLM, key, 1);
                int   pi = __shfl_up_sync(FULLM, idx, 1);
                if (v < key) {
                    if (lane > 0 && v < pk) { key = pk; idx = pi; }
                    else                    { key = v;  idx = vi; }
                }
                thresh = __shfl_sync(FULLM, key, 15);
            }
        }
    }

    if (half == 1 && lane < 16) { sD[wq][lane] = key; sI[wq][lane] = idx; }
    __syncthreads();

    if (half == 0) {
        // merge the other warp's sorted 16 (ascending -> early break)
        for (int n = 0; n < 16; n++) {
            float v  = sD[wq][n];
            if (v >= thresh) break;
            int   vi = sI[wq][n];
            float pk = __shfl_up_sync(FULLM, key, 1);
            int   pi = __shfl_up_sync(FULLM, idx, 1);
            if (v < key) {
                if (lane > 0 && v < pk) { key = pk; idx = pi; }
                else                    { key = v;  idx = vi; }
            }
            thresh = __shfl_sync(FULLM, key, 15);
        }
        if (lane < KNN) g_idx[(base + qi)*KNN + lane] = base + idx;  // GLOBAL
    }
}

// ---------------------------------------------------------------------------
// Precompute Q[n], P[n]: warp per point, W1 staged in smem.
// ---------------------------------------------------------------------------
__global__ void __launch_bounds__(256) precomp_kernel(
    const float* __restrict__ verts, const float* __restrict__ feat,
    const float* __restrict__ W1, const float* __restrict__ b1)
{
    __shared__ float sW1[EIN*HID];   // 34.3KB
    int tid = threadIdx.x, lane = tid & 31, w = tid >> 5;
    for (int e = tid; e < EIN*HID; e += 256) sW1[e] = W1[e];
    __syncthreads();

    int p = blockIdx.x * 8 + w;
    float4 f4 = make_float4(0.f,0.f,0.f,0.f);
    if (lane < 8) f4 = *(const float4*)&feat[p*CIN + lane*4];
    float vx = verts[p*3+0], vy = verts[p*3+1], vz = verts[p*3+2];

    int c = lane*4;
    float4 q  = make_float4(0.f,0.f,0.f,0.f);
    float4 pp = *(const float4*)&b1[c];

#pragma unroll
    for (int src = 0; src < 8; src++) {
        float fx = __shfl_sync(FULLM, f4.x, src);
        float fy = __shfl_sync(FULLM, f4.y, src);
        float fz = __shfl_sync(FULLM, f4.z, src);
        float fw = __shfl_sync(FULLM, f4.w, src);
        float fv[4] = {fx, fy, fz, fw};
        int k0 = src*4;
#pragma unroll
        for (int kk = 0; kk < 4; kk++) {
            int k = k0 + kk;
            float4 wa = *(const float4*)&sW1[k*HID + c];          // W1a row k
            float4 wb = *(const float4*)&sW1[(CIN + k)*HID + c];  // W1b row k
            q.x  = fmaf(fv[kk], wa.x, q.x);  q.y  = fmaf(fv[kk], wa.y, q.y);
            q.z  = fmaf(fv[kk], wa.z, q.z);  q.w  = fmaf(fv[kk], wa.w, q.w);
            pp.x = fmaf(fv[kk], wb.x, pp.x); pp.y = fmaf(fv[kk], wb.y, pp.y);
            pp.z = fmaf(fv[kk], wb.z, pp.z); pp.w = fmaf(fv[kk], wb.w, pp.w);
        }
    }
    // vertex rows (W1c): Q += v@W1c ; P -= v@W1c
    float vv[3] = {vx, vy, vz};
#pragma unroll
    for (int k = 0; k < 3; k++) {
        float4 wc = *(const float4*)&sW1[(2*CIN + k)*HID + c];
        q.x  = fmaf(vv[k],  wc.x, q.x);  q.y  = fmaf(vv[k],  wc.y, q.y);
        q.z  = fmaf(vv[k],  wc.z, q.z);  q.w  = fmaf(vv[k],  wc.w, q.w);
        pp.x = fmaf(-vv[k], wc.x, pp.x); pp.y = fmaf(-vv[k], wc.y, pp.y);
        pp.z = fmaf(-vv[k], wc.z, pp.z); pp.w = fmaf(-vv[k], wc.w, pp.w);
    }
    *(float4*)&g_q[p*HID + c] = q;
    *(float4*)&g_p[p*HID + c] = pp;
}

// ---------------------------------------------------------------------------
// GELU (tanh form) via exp: gelu(x) = x * (1 - 1/(1+e^{2z})), z = 0.7979(x+0.044715x^3)
// ---------------------------------------------------------------------------
__device__ __forceinline__ float gelu_fast(float x) {
    float z2 = 1.5957691216057308f * fmaf(0.044715f * x * x, x, x);
    float e  = __expf(z2);
    float r  = __fdividef(1.0f, e + 1.0f);
    return x - x * r;
}

// ---------------------------------------------------------------------------
// Edge kernel: warp per point. For each of 16 neighbors: h = Q[nb] + P[p],
// LN (warp reduce), GELU, accumulate mean. Then fused G@W2 + b2 -> g_mid.
// ---------------------------------------------------------------------------
__global__ void __launch_bounds__(256) edge_kernel(
    const float* __restrict__ g1, const float* __restrict__ be1,
    const float* __restrict__ W2, const float* __restrict__ b2)
{
    __shared__ float sW2[HID*COUT];   // 32KB
    int tid = threadIdx.x, lane = tid & 31, w = tid >> 5;
    for (int e = tid; e < HID*COUT; e += 256) sW2[e] = W2[e];
    __syncthreads();

    int p = blockIdx.x * 8 + w;
    int myidx = (lane < KNN) ? g_idx[p*KNN + lane] : 0;
    int c = lane * 4;

    float4 P4  = *(const float4*)&g_p[p*HID + c];
    float4 g1v = *(const float4*)&g1[c];
    float4 bev = *(const float4*)&be1[c];

    float4 accG = make_float4(0.f,0.f,0.f,0.f);

    int nb = __shfl_sync(FULLM, myidx, 0);
    float4 qn = __ldg((const float4*)&g_q[nb*HID + c]);

#pragma unroll 4
    for (int n = 0; n < KNN; n++) {
        float4 h;
        h.x = qn.x + P4.x; h.y = qn.y + P4.y;
        h.z = qn.z + P4.z; h.w = qn.w + P4.w;
        if (n + 1 < KNN) {
            int nb2 = __shfl_sync(FULLM, myidx, n+1);
            qn = __ldg((const float4*)&g_q[nb2*HID + c]);
        }
        float s  = (h.x + h.y) + (h.z + h.w);
        float s2 = fmaf(h.x,h.x, fmaf(h.y,h.y, fmaf(h.z,h.z, h.w*h.w)));
#pragma unroll
        for (int off = 16; off; off >>= 1) {
            s  += __shfl_xor_sync(FULLM, s,  off);
            s2 += __shfl_xor_sync(FULLM, s2, off);
        }
        float mu  = s  * (1.f/HID);
        float var = s2 * (1.f/HID) - mu*mu;
        float rs  = rsqrtf(var + 1e-5f);
        accG.x += gelu_fast(fmaf((h.x - mu)*rs, g1v.x, bev.x));
        accG.y += gelu_fast(fmaf((h.y - mu)*rs, g1v.y, bev.y));
        accG.z += gelu_fast(fmaf((h.z - mu)*rs, g1v.z, bev.z));
        accG.w += gelu_fast(fmaf((h.w - mu)*rs, g1v.w, bev.w));
    }
    accG.x *= (1.f/KNN); accG.y *= (1.f/KNN);
    accG.z *= (1.f/KNN); accG.w *= (1.f/KNN);

    // fused mid = G @ W2 + b2  (lane handles cols lane, lane+32)
    float m0 = __ldg(&b2[lane]);
    float m1 = __ldg(&b2[lane + 32]);
#pragma unroll
    for (int src = 0; src < 32; src++) {
        float gx = __shfl_sync(FULLM, accG.x, src);
        float gy = __shfl_sync(FULLM, accG.y, src);
        float gz = __shfl_sync(FULLM, accG.z, src);
        float gw = __shfl_sync(FULLM, accG.w, src);
        int k0 = src * 4;
        m0 = fmaf(gx, sW2[(k0+0)*COUT + lane], m0);
        m0 = fmaf(gy, sW2[(k0+1)*COUT + lane], m0);
        m0 = fmaf(gz, sW2[(k0+2)*COUT + lane], m0);
        m0 = fmaf(gw, sW2[(k0+3)*COUT + lane], m0);
        m1 = fmaf(gx, sW2[(k0+0)*COUT + lane + 32], m1);
        m1 = fmaf(gy, sW2[(k0+1)*COUT + lane + 32], m1);
        m1 = fmaf(gz, sW2[(k0+2)*COUT + lane + 32], m1);
        m1 = fmaf(gw, sW2[(k0+3)*COUT + lane + 32], m1);
    }
    g_mid[p*COUT + lane]      = m0;
    g_mid[p*COUT + lane + 32] = m1;
}

// ---------------------------------------------------------------------------
// MLP2 fused: 64 points per block, 82KB smem -> 2 blocks/SM, grid 256.
// ---------------------------------------------------------------------------
#define M2PTS 64
#define SMEM2_FLOATS (COUT*M2PTS + COUT*HID + HID*COUT)  // 4096+8192+8192 = 20480

__global__ void __launch_bounds__(256, 2) mlp2_kernel(
    const float* __restrict__ Wo1, const float* __restrict__ bo1,
    const float* __restrict__ go,  const float* __restrict__ beo,
    const float* __restrict__ Wo2, const float* __restrict__ bo2,
    float* __restrict__ out)
{
    extern __shared__ float sm[];
    float* sAt  = sm;                       // [64 k][64 rows]
    float* sWo1 = sm + COUT*M2PTS;          // [64 k][128]
    float* sH   = sm;                       // [64 rows][132] aliases sAt+sWo1 (8448<=12288)
    float* sWo2 = sm + COUT*M2PTS + COUT*HID;  // [128 k][64]

    int tid = threadIdx.x;
    int r0  = blockIdx.x * M2PTS;

    for (int e = tid; e < COUT*HID; e += 256) sWo1[e] = Wo1[e];
    for (int e = tid; e < HID*COUT; e += 256) sWo2[e] = Wo2[e];
    for (int e = tid; e < COUT*M2PTS; e += 256) {
        int r = e & (M2PTS-1), k = e >> 6;
        sAt[k*M2PTS + r] = g_mid[(r0 + r)*COUT + k];
    }
    __syncthreads();

    int tx = tid & 15, ty = tid >> 4;

    // stage 1: [64,64] @ [64,128] -> acc[4][8]
    float acc[4][8];
#pragma unroll
    for (int i = 0; i < 4; i++)
#pragma unroll
        for (int j = 0; j < 8; j++) acc[i][j] = 0.f;

    for (int k = 0; k < COUT; k++) {
        float4 a4 = *(const float4*)&sAt[k*M2PTS + ty*4];
        float4 c0 = *(const float4*)&sWo1[k*HID + tx*8];
        float4 c1 = *(const float4*)&sWo1[k*HID + tx*8 + 4];
        float a[4] = {a4.x,a4.y,a4.z,a4.w};
        float wv[8] = {c0.x,c0.y,c0.z,c0.w,c1.x,c1.y,c1.z,c1.w};
#pragma unroll
        for (int i = 0; i < 4; i++)
#pragma unroll
            for (int j = 0; j < 8; j++)
                acc[i][j] = fmaf(a[i], wv[j], acc[i][j]);
    }

    __syncthreads();   // sAt/sWo1 reads done; sH may overwrite

    float b1j[8], gj[8], bej[8];
#pragma unroll
    for (int j = 0; j < 8; j++) {
        int col = tx*8 + j;
        b1j[j] = bo1[col]; gj[j] = go[col]; bej[j] = beo[col];
    }
#pragma unroll
    for (int i = 0; i < 4; i++) {
        float ps = 0.f, ps2 = 0.f;
#pragma unroll
        for (int j = 0; j < 8; j++) {
            float h = acc[i][j] + b1j[j];
            acc[i][j] = h;
            ps += h; ps2 = fmaf(h, h, ps2);
        }
#pragma unroll
        for (int off = 8; off; off >>= 1) {
            ps  += __shfl_xor_sync(FULLM, ps,  off);
            ps2 += __shfl_xor_sync(FULLM, ps2, off);
        }
        float mu  = ps  * (1.f/HID);
        float var = ps2 * (1.f/HID) - mu*mu;
        float rs  = rsqrtf(var + 1e-5f);
        float o[8];
#pragma unroll
        for (int j = 0; j < 8; j++)
            o[j] = gelu_fast(fmaf((acc[i][j] - mu)*rs, gj[j], bej[j]));
        int row = ty*4 + i;
        *(float4*)&sH[row*132 + tx*8]     = make_float4(o[0],o[1],o[2],o[3]);
        *(float4*)&sH[row*132 + tx*8 + 4] = make_float4(o[4],o[5],o[6],o[7]);
    }
    __syncthreads();

    // stage 3: [64,128] @ [128,64] -> acc2[4][4]
    float acc2[4][4];
#pragma unroll
    for (int i = 0; i < 4; i++)
#pragma unroll
        for (int j = 0; j < 4; j++) acc2[i][j] = 0.f;

    for (int k = 0; k < HID; k += 4) {
        float4 w0 = *(const float4*)&sWo2[(k+0)*COUT + tx*4];
        float4 w1 = *(const float4*)&sWo2[(k+1)*COUT + tx*4];
        float4 w2 = *(const float4*)&sWo2[(k+2)*COUT + tx*4];
        float4 w3 = *(const float4*)&sWo2[(k+3)*COUT + tx*4];
#pragma unroll
        for (int i = 0; i < 4; i++) {
            float4 av = *(const float4*)&sH[(ty*4+i)*132 + k];
            acc2[i][0] = fmaf(av.x, w0.x, fmaf(av.y, w1.x, fmaf(av.z, w2.x, fmaf(av.w, w3.x, acc2[i][0]))));
            acc2[i][1] = fmaf(av.x, w0.y, fmaf(av.y, w1.y, fmaf(av.z, w2.y, fmaf(av.w, w3.y, acc2[i][1]))));
            acc2[i][2] = fmaf(av.x, w0.z, fmaf(av.y, w1.z, fmaf(av.z, w2.z, fmaf(av.w, w3.z, acc2[i][2]))));
            acc2[i][3] = fmaf(av.x, w0.w, fmaf(av.y, w1.w, fmaf(av.z, w2.w, fmaf(av.w, w3.w, acc2[i][3]))));
        }
    }

    float b2j[4];
#pragma unroll
    for (int j = 0; j < 4; j++) b2j[j] = bo2[tx*4 + j];
#pragma unroll
    for (int i = 0; i < 4; i++) {
        int row = r0 + ty*4 + i;
#pragma unroll
        for (int j = 0; j < 4; j++)
            out[row*COUT + tx*4 + j] = acc2[i][j] + b2j[j];
    }
}

// ---------------------------------------------------------------------------
extern "C" void kernel_launch(void* const* d_in, const int* in_sizes, int n_in,
                              void* d_out, int out_size) {
    const float* verts = (const float*)d_in[0];
    const float* feat  = (const float*)d_in[1];
    const float* W1    = (const float*)d_in[2];
    const float* b1    = (const float*)d_in[3];
    const float* g1    = (const float*)d_in[4];
    const float* be1   = (const float*)d_in[5];
    const float* W2    = (const float*)d_in[6];
    const float* b2    = (const float*)d_in[7];
    const float* Wo1   = (const float*)d_in[8];
    const float* bo1   = (const float*)d_in[9];
    const float* go    = (const float*)d_in[10];
    const float* beo   = (const float*)d_in[11];
    const float* Wo2   = (const float*)d_in[12];
    const float* bo2   = (const float*)d_in[13];
    float* out = (float*)d_out;

    const int smem2 = SMEM2_FLOATS * 4;   // 81920
    cudaFuncSetAttribute(mlp2_kernel, cudaFuncAttributeMaxDynamicSharedMemorySize, smem2);

    prep_kernel<<<(TOT + 255)/256, 256>>>(verts);
    knn_kernel<<<TOT/4, 256>>>();                          // 2 warps per query
    precomp_kernel<<<TOT/8, 256>>>(verts, feat, W1, b1);
    edge_kernel<<<TOT/8, 256>>>(g1, be1, W2, b2);
    mlp2_kernel<<<TOT/M2PTS, 256, smem2>>>(Wo1, bo1, go, beo, Wo2, bo2, out);
}

// round 5
// speedup vs baseline: 6.8358x; 1.0483x over previous
#include <cuda_runtime.h>
#include <math.h>

#define BN   2
#define NPTS 8192
#define KNN  16
#define CIN  32
#define EIN  67      // 32 + 32 + 3
#define HID  128
#define COUT 64
#define TOT  (BN*NPTS)
#define FULLM 0xffffffffu

// Scratch (no allocations allowed)
__device__ int    g_idx[TOT*KNN];          // GLOBAL neighbor indices
__device__ float  g_mid[TOT*COUT];
__device__ float4 g_vert4[TOT];
__device__ float  g_q[TOT*HID];            // Q[n] = feat@W1a + vert@W1c
__device__ float  g_p[TOT*HID];            // P[n] = feat@W1b + b1 - vert@W1c

// ---------------------------------------------------------------------------
__global__ void prep_kernel(const float* __restrict__ verts) {
    int i = blockIdx.x * blockDim.x + threadIdx.x;
    if (i < TOT) {
        float x = verts[i*3+0], y = verts[i*3+1], z = verts[i*3+2];
        g_vert4[i] = make_float4(x, y, z, x*x + y*y + z*z);
    }
}

// ---------------------------------------------------------------------------
// KNN: one warp handles FOUR queries. Each 32-candidate batch is loaded once
// (1 LDG.128/lane) and scored against all 4 register-resident queries ->
// candidate bytes per query drop 4x (the scan was L1-wavefront-bound).
// Per query: ascending lane-sorted best-32 queue, threshold = lane 15.
// Distance formula identical (same FMA order) to prior rounds.
// ---------------------------------------------------------------------------
__global__ void __launch_bounds__(256) knn_kernel() {
    int tid  = threadIdx.x;
    int lane = tid & 31;
    int w    = tid >> 5;
    int qg   = (blockIdx.x * 8 + w) * 4;   // first of 4 consecutive queries
    int b    = qg >> 13;
    int base = b * NPTS;
    int q0   = qg & (NPTS - 1);

    float qx[4], qy[4], qz[4], qs[4];
#pragma unroll
    for (int r = 0; r < 4; r++) {
        float4 qv = g_vert4[base + q0 + r];
        qx[r] = qv.x; qy[r] = qv.y; qz[r] = qv.z; qs[r] = qv.w;
    }

    float key[4], th[4];
    int   idx[4];
#pragma unroll
    for (int r = 0; r < 4; r++) { key[r] = 3.4e38f; idx[r] = 0; th[r] = 3.4e38f; }

    for (int i = 0; i < NPTS/32; i++) {
        float4 c = g_vert4[base + i*32 + lane];
        float d[4];
#pragma unroll
        for (int r = 0; r < 4; r++) {
            float dot = fmaf(qx[r], c.x, fmaf(qy[r], c.y, qz[r]*c.z));
            d[r] = fmaf(-2.0f, dot, qs[r] + c.w);
        }
#pragma unroll
        for (int r = 0; r < 4; r++) {
            unsigned mask = __ballot_sync(FULLM, d[r] < th[r]);
            while (mask) {
                int src = __ffs(mask) - 1;
                mask &= mask - 1;
                float v  = __shfl_sync(FULLM, d[r], src);
                int   vi = i*32 + src;
                if (v < th[r]) {
                    float pk = __shfl_up_sync(FULLM, key[r], 1);
                    int   pi = __shfl_up_sync(FULLM, idx[r], 1);
                    if (v < key[r]) {
                        if (lane > 0 && v < pk) { key[r] = pk; idx[r] = pi; }
                        else                    { key[r] = v;  idx[r] = vi; }
                    }
                    th[r] = __shfl_sync(FULLM, key[r], 15);
                }
            }
        }
    }

    if (lane < KNN) {
#pragma unroll
        for (int r = 0; r < 4; r++)
            g_idx[(base + q0 + r)*KNN + lane] = base + idx[r];
    }
}

// ---------------------------------------------------------------------------
// Precompute Q[n], P[n]: warp per point, W1 staged in smem.
// ---------------------------------------------------------------------------
__global__ void __launch_bounds__(256) precomp_kernel(
    const float* __restrict__ verts, const float* __restrict__ feat,
    const float* __restrict__ W1, const float* __restrict__ b1)
{
    __shared__ float sW1[EIN*HID];   // 34.3KB
    int tid = threadIdx.x, lane = tid & 31, w = tid >> 5;
    for (int e = tid; e < EIN*HID; e += 256) sW1[e] = W1[e];
    __syncthreads();

    int p = blockIdx.x * 8 + w;
    float4 f4 = make_float4(0.f,0.f,0.f,0.f);
    if (lane < 8) f4 = *(const float4*)&feat[p*CIN + lane*4];
    float vx = verts[p*3+0], vy = verts[p*3+1], vz = verts[p*3+2];

    int c = lane*4;
    float4 q  = make_float4(0.f,0.f,0.f,0.f);
    float4 pp = *(const float4*)&b1[c];

#pragma unroll
    for (int src = 0; src < 8; src++) {
        float fx = __shfl_sync(FULLM, f4.x, src);
        float fy = __shfl_sync(FULLM, f4.y, src);
        float fz = __shfl_sync(FULLM, f4.z, src);
        float fw = __shfl_sync(FULLM, f4.w, src);
        float fv[4] = {fx, fy, fz, fw};
        int k0 = src*4;
#pragma unroll
        for (int kk = 0; kk < 4; kk++) {
            int k = k0 + kk;
            float4 wa = *(const float4*)&sW1[k*HID + c];          // W1a row k
            float4 wb = *(const float4*)&sW1[(CIN + k)*HID + c];  // W1b row k
            q.x  = fmaf(fv[kk], wa.x, q.x);  q.y  = fmaf(fv[kk], wa.y, q.y);
            q.z  = fmaf(fv[kk], wa.z, q.z);  q.w  = fmaf(fv[kk], wa.w, q.w);
            pp.x = fmaf(fv[kk], wb.x, pp.x); pp.y = fmaf(fv[kk], wb.y, pp.y);
            pp.z = fmaf(fv[kk], wb.z, pp.z); pp.w = fmaf(fv[kk], wb.w, pp.w);
        }
    }
    float vv[3] = {vx, vy, vz};
#pragma unroll
    for (int k = 0; k < 3; k++) {
        float4 wc = *(const float4*)&sW1[(2*CIN + k)*HID + c];
        q.x  = fmaf(vv[k],  wc.x, q.x);  q.y  = fmaf(vv[k],  wc.y, q.y);
        q.z  = fmaf(vv[k],  wc.z, q.z);  q.w  = fmaf(vv[k],  wc.w, q.w);
        pp.x = fmaf(-vv[k], wc.x, pp.x); pp.y = fmaf(-vv[k], wc.y, pp.y);
        pp.z = fmaf(-vv[k], wc.z, pp.z); pp.w = fmaf(-vv[k], wc.w, pp.w);
    }
    *(float4*)&g_q[p*HID + c] = q;
    *(float4*)&g_p[p*HID + c] = pp;
}

// ---------------------------------------------------------------------------
__device__ __forceinline__ float gelu_fast(float x) {
    float z2 = 1.5957691216057308f * fmaf(0.044715f * x * x, x, x);
    float e  = __expf(z2);
    float r  = __fdividef(1.0f, e + 1.0f);
    return x - x * r;
}

// ---------------------------------------------------------------------------
// Edge kernel: warp per point, TWO neighbors per iteration so the two
// (s, s2) butterfly chains interleave (the shfl chain is latency-bound).
// ---------------------------------------------------------------------------
__global__ void __launch_bounds__(256) edge_kernel(
    const float* __restrict__ g1, const float* __restrict__ be1,
    const float* __restrict__ W2, const float* __restrict__ b2)
{
    __shared__ float sW2[HID*COUT];   // 32KB
    int tid = threadIdx.x, lane = tid & 31, w = tid >> 5;
    for (int e = tid; e < HID*COUT; e += 256) sW2[e] = W2[e];
    __syncthreads();

    int p = blockIdx.x * 8 + w;
    int myidx = (lane < KNN) ? g_idx[p*KNN + lane] : 0;
    int c = lane * 4;

    float4 P4  = *(const float4*)&g_p[p*HID + c];
    float4 g1v = *(const float4*)&g1[c];
    float4 bev = *(const float4*)&be1[c];

    float4 accG = make_float4(0.f,0.f,0.f,0.f);

    int nb0 = __shfl_sync(FULLM, myidx, 0);
    int nb1 = __shfl_sync(FULLM, myidx, 1);
    float4 qa = __ldg((const float4*)&g_q[nb0*HID + c]);
    float4 qb = __ldg((const float4*)&g_q[nb1*HID + c]);

#pragma unroll
    for (int n = 0; n < KNN; n += 2) {
        float4 h0, h1;
        h0.x = qa.x + P4.x; h0.y = qa.y + P4.y; h0.z = qa.z + P4.z; h0.w = qa.w + P4.w;
        h1.x = qb.x + P4.x; h1.y = qb.y + P4.y; h1.z = qb.z + P4.z; h1.w = qb.w + P4.w;
        if (n + 2 < KNN) {
            int na = __shfl_sync(FULLM, myidx, n+2);
            int nbx = __shfl_sync(FULLM, myidx, n+3);
            qa = __ldg((const float4*)&g_q[na*HID + c]);
            qb = __ldg((const float4*)&g_q[nbx*HID + c]);
        }
        float s0  = (h0.x + h0.y) + (h0.z + h0.w);
        float s20 = fmaf(h0.x,h0.x, fmaf(h0.y,h0.y, fmaf(h0.z,h0.z, h0.w*h0.w)));
        float s1  = (h1.x + h1.y) + (h1.z + h1.w);
        float s21 = fmaf(h1.x,h1.x, fmaf(h1.y,h1.y, fmaf(h1.z,h1.z, h1.w*h1.w)));
#pragma unroll
        for (int off = 16; off; off >>= 1) {
            s0  += __shfl_xor_sync(FULLM, s0,  off);
            s1  += __shfl_xor_sync(FULLM, s1,  off);
            s20 += __shfl_xor_sync(FULLM, s20, off);
            s21 += __shfl_xor_sync(FULLM, s21, off);
        }
        float mu0  = s0  * (1.f/HID);
        float var0 = s20 * (1.f/HID) - mu0*mu0;
        float rs0  = rsqrtf(var0 + 1e-5f);
        float mu1  = s1  * (1.f/HID);
        float var1 = s21 * (1.f/HID) - mu1*mu1;
        float rs1  = rsqrtf(var1 + 1e-5f);
        accG.x += gelu_fast(fmaf((h0.x - mu0)*rs0, g1v.x, bev.x));
        accG.y += gelu_fast(fmaf((h0.y - mu0)*rs0, g1v.y, bev.y));
        accG.z += gelu_fast(fmaf((h0.z - mu0)*rs0, g1v.z, bev.z));
        accG.w += gelu_fast(fmaf((h0.w - mu0)*rs0, g1v.w, bev.w));
        accG.x += gelu_fast(fmaf((h1.x - mu1)*rs1, g1v.x, bev.x));
        accG.y += gelu_fast(fmaf((h1.y - mu1)*rs1, g1v.y, bev.y));
        accG.z += gelu_fast(fmaf((h1.z - mu1)*rs1, g1v.z, bev.z));
        accG.w += gelu_fast(fmaf((h1.w - mu1)*rs1, g1v.w, bev.w));
    }
    accG.x *= (1.f/KNN); accG.y *= (1.f/KNN);
    accG.z *= (1.f/KNN); accG.w *= (1.f/KNN);

    // fused mid = G @ W2 + b2  (lane handles cols lane, lane+32)
    float m0 = __ldg(&b2[lane]);
    float m1 = __ldg(&b2[lane + 32]);
#pragma unroll
    for (int src = 0; src < 32; src++) {
        float gx = __shfl_sync(FULLM, accG.x, src);
        float gy = __shfl_sync(FULLM, accG.y, src);
        float gz = __shfl_sync(FULLM, accG.z, src);
        float gw = __shfl_sync(FULLM, accG.w, src);
        int k0 = src * 4;
        m0 = fmaf(gx, sW2[(k0+0)*COUT + lane], m0);
        m0 = fmaf(gy, sW2[(k0+1)*COUT + lane], m0);
        m0 = fmaf(gz, sW2[(k0+2)*COUT + lane], m0);
        m0 = fmaf(gw, sW2[(k0+3)*COUT + lane], m0);
        m1 = fmaf(gx, sW2[(k0+0)*COUT + lane + 32], m1);
        m1 = fmaf(gy, sW2[(k0+1)*COUT + lane + 32], m1);
        m1 = fmaf(gz, sW2[(k0+2)*COUT + lane + 32], m1);
        m1 = fmaf(gw, sW2[(k0+3)*COUT + lane + 32], m1);
    }
    g_mid[p*COUT + lane]      = m0;
    g_mid[p*COUT + lane + 32] = m1;
}

// ---------------------------------------------------------------------------
// MLP2 fused: 64 points per block, 82KB smem -> 2 blocks/SM, grid 256.
// ---------------------------------------------------------------------------
#define M2PTS 64
#define SMEM2_FLOATS (COUT*M2PTS + COUT*HID + HID*COUT)  // 20480

__global__ void __launch_bounds__(256, 2) mlp2_kernel(
    const float* __restrict__ Wo1, const float* __restrict__ bo1,
    const float* __restrict__ go,  const float* __restrict__ beo,
    const float* __restrict__ Wo2, const float* __restrict__ bo2,
    float* __restrict__ out)
{
    extern __shared__ float sm[];
    float* sAt  = sm;                       // [64 k][64 rows]
    float* sWo1 = sm + COUT*M2PTS;          // [64 k][128]
    float* sH   = sm;                       // [64 rows][132] aliases sAt+sWo1
    float* sWo2 = sm + COUT*M2PTS + COUT*HID;  // [128 k][64]

    int tid = threadIdx.x;
    int r0  = blockIdx.x * M2PTS;

    for (int e = tid; e < COUT*HID; e += 256) sWo1[e] = Wo1[e];
    for (int e = tid; e < HID*COUT; e += 256) sWo2[e] = Wo2[e];
    for (int e = tid; e < COUT*M2PTS; e += 256) {
        int r = e & (M2PTS-1), k = e >> 6;
        sAt[k*M2PTS + r] = g_mid[(r0 + r)*COUT + k];
    }
    __syncthreads();

    int tx = tid & 15, ty = tid >> 4;

    float acc[4][8];
#pragma unroll
    for (int i = 0; i < 4; i++)
#pragma unroll
        for (int j = 0; j < 8; j++) acc[i][j] = 0.f;

    for (int k = 0; k < COUT; k++) {
        float4 a4 = *(const float4*)&sAt[k*M2PTS + ty*4];
        float4 c0 = *(const float4*)&sWo1[k*HID + tx*8];
        float4 c1 = *(const float4*)&sWo1[k*HID + tx*8 + 4];
        float a[4] = {a4.x,a4.y,a4.z,a4.w};
        float wv[8] = {c0.x,c0.y,c0.z,c0.w,c1.x,c1.y,c1.z,c1.w};
#pragma unroll
        for (int i = 0; i < 4; i++)
#pragma unroll
            for (int j = 0; j < 8; j++)
                acc[i][j] = fmaf(a[i], wv[j], acc[i][j]);
    }

    __syncthreads();

    float b1j[8], gj[8], bej[8];
#pragma unroll
    for (int j = 0; j < 8; j++) {
        int col = tx*8 + j;
        b1j[j] = bo1[col]; gj[j] = go[col]; bej[j] = beo[col];
    }
#pragma unroll
    for (int i = 0; i < 4; i++) {
        float ps = 0.f, ps2 = 0.f;
#pragma unroll
        for (int j = 0; j < 8; j++) {
            float h = acc[i][j] + b1j[j];
            acc[i][j] = h;
            ps += h; ps2 = fmaf(h, h, ps2);
        }
#pragma unroll
        for (int off = 8; off; off >>= 1) {
            ps  += __shfl_xor_sync(FULLM, ps,  off);
            ps2 += __shfl_xor_sync(FULLM, ps2, off);
        }
        float mu  = ps  * (1.f/HID);
        float var = ps2 * (1.f/HID) - mu*mu;
        float rs  = rsqrtf(var + 1e-5f);
        float o[8];
#pragma unroll
        for (int j = 0; j < 8; j++)
            o[j] = gelu_fast(fmaf((acc[i][j] - mu)*rs, gj[j], bej[j]));
        int row = ty*4 + i;
        *(float4*)&sH[row*132 + tx*8]     = make_float4(o[0],o[1],o[2],o[3]);
        *(float4*)&sH[row*132 + tx*8 + 4] = make_float4(o[4],o[5],o[6],o[7]);
    }
    __syncthreads();

    float acc2[4][4];
#pragma unroll
    for (int i = 0; i < 4; i++)
#pragma unroll
        for (int j = 0; j < 4; j++) acc2[i][j] = 0.f;

    for (int k = 0; k < HID; k += 4) {
        float4 w0 = *(const float4*)&sWo2[(k+0)*COUT + tx*4];
        float4 w1 = *(const float4*)&sWo2[(k+1)*COUT + tx*4];
        float4 w2 = *(const float4*)&sWo2[(k+2)*COUT + tx*4];
        float4 w3 = *(const float4*)&sWo2[(k+3)*COUT + tx*4];
#pragma unroll
        for (int i = 0; i < 4; i++) {
            float4 av = *(const float4*)&sH[(ty*4+i)*132 + k];
            acc2[i][0] = fmaf(av.x, w0.x, fmaf(av.y, w1.x, fmaf(av.z, w2.x, fmaf(av.w, w3.x, acc2[i][0]))));
            acc2[i][1] = fmaf(av.x, w0.y, fmaf(av.y, w1.y, fmaf(av.z, w2.y, fmaf(av.w, w3.y, acc2[i][1]))));
            acc2[i][2] = fmaf(av.x, w0.z, fmaf(av.y, w1.z, fmaf(av.z, w2.z, fmaf(av.w, w3.z, acc2[i][2]))));
            acc2[i][3] = fmaf(av.x, w0.w, fmaf(av.y, w1.w, fmaf(av.z, w2.w, fmaf(av.w, w3.w, acc2[i][3]))));
        }
    }

    float b2j[4];
#pragma unroll
    for (int j = 0; j < 4; j++) b2j[j] = bo2[tx*4 + j];
#pragma unroll
    for (int i = 0; i < 4; i++) {
        int row = r0 + ty*4 + i;
#pragma unroll
        for (int j = 0; j < 4; j++)
            out[row*COUT + tx*4 + j] = acc2[i][j] + b2j[j];
    }
}

// ---------------------------------------------------------------------------
extern "C" void kernel_launch(void* const* d_in, const int* in_sizes, int n_in,
                              void* d_out, int out_size) {
    const float* verts = (const float*)d_in[0];
    const float* feat  = (const float*)d_in[1];
    const float* W1    = (const float*)d_in[2];
    const float* b1    = (const float*)d_in[3];
    const float* g1    = (const float*)d_in[4];
    const float* be1   = (const float*)d_in[5];
    const float* W2    = (const float*)d_in[6];
    const float* b2    = (const float*)d_in[7];
    const float* Wo1   = (const float*)d_in[8];
    const float* bo1   = (const float*)d_in[9];
    const float* go    = (const float*)d_in[10];
    const float* beo   = (const float*)d_in[11];
    const float* Wo2   = (const float*)d_in[12];
    const float* bo2   = (const float*)d_in[13];
    float* out = (float*)d_out;

    const int smem2 = SMEM2_FLOATS * 4;   // 81920
    cudaFuncSetAttribute(mlp2_kernel, cudaFuncAttributeMaxDynamicSharedMemorySize, smem2);

    prep_kernel<<<(TOT + 255)/256, 256>>>(verts);
    knn_kernel<<<TOT/32, 256>>>();                         // 4 queries per warp
    precomp_kernel<<<TOT/8, 256>>>(verts, feat, W1, b1);
    edge_kernel<<<TOT/8, 256>>>(g1, be1, W2, b2);
    mlp2_kernel<<<TOT/M2PTS, 256, smem2>>>(Wo1, bo1, go, beo, Wo2, bo2, out);
}

// round 6
// speedup vs baseline: 7.0344x; 1.0290x over previous
#include <cuda_runtime.h>
#include <math.h>

#define BN   2
#define NPTS 8192
#define KNN  16
#define CIN  32
#define EIN  67      // 32 + 32 + 3
#define HID  128
#define COUT 64
#define TOT  (BN*NPTS)
#define FULLM 0xffffffffu

// Scratch (no allocations allowed)
__device__ int    g_idx[TOT*KNN];          // GLOBAL neighbor indices
__device__ float  g_mid[TOT*COUT];
__device__ float4 g_vert4[TOT];
__device__ float  g_q[TOT*HID];            // Q[n] = feat@W1a + vert@W1c
__device__ float  g_p[TOT*HID];            // P[n] = feat@W1b + b1 - vert@W1c

// ---------------------------------------------------------------------------
__global__ void prep_kernel(const float* __restrict__ verts) {
    int i = blockIdx.x * blockDim.x + threadIdx.x;
    if (i < TOT) {
        float x = verts[i*3+0], y = verts[i*3+1], z = verts[i*3+2];
        g_vert4[i] = make_float4(x, y, z, x*x + y*y + z*z);
    }
}

// ---------------------------------------------------------------------------
// KNN: one warp handles TWO queries (R=2). Each 32-candidate batch is loaded
// once and scored against both register-resident queries. 8192 warps total
// (13.8/SMSP) hide the dependent-shuffle latency of the sorted-queue inserts.
// Per query: ascending lane-sorted best-32 queue, threshold = lane 15.
// ---------------------------------------------------------------------------
__global__ void __launch_bounds__(256) knn_kernel() {
    int tid  = threadIdx.x;
    int lane = tid & 31;
    int w    = tid >> 5;
    int qg   = (blockIdx.x * 8 + w) * 2;   // first of 2 consecutive queries
    int b    = qg >> 13;
    int base = b * NPTS;
    int q0   = qg & (NPTS - 1);

    float qx[2], qy[2], qz[2], qs[2];
#pragma unroll
    for (int r = 0; r < 2; r++) {
        float4 qv = g_vert4[base + q0 + r];
        qx[r] = qv.x; qy[r] = qv.y; qz[r] = qv.z; qs[r] = qv.w;
    }

    float key[2], th[2];
    int   idx[2];
#pragma unroll
    for (int r = 0; r < 2; r++) { key[r] = 3.4e38f; idx[r] = 0; th[r] = 3.4e38f; }

    for (int i = 0; i < NPTS/32; i++) {
        float4 c = g_vert4[base + i*32 + lane];
        float d[2];
#pragma unroll
        for (int r = 0; r < 2; r++) {
            float dot = fmaf(qx[r], c.x, fmaf(qy[r], c.y, qz[r]*c.z));
            d[r] = fmaf(-2.0f, dot, qs[r] + c.w);
        }
#pragma unroll
        for (int r = 0; r < 2; r++) {
            unsigned mask = __ballot_sync(FULLM, d[r] < th[r]);
            while (mask) {
                int src = __ffs(mask) - 1;
                mask &= mask - 1;
                float v  = __shfl_sync(FULLM, d[r], src);
                int   vi = i*32 + src;
                if (v < th[r]) {
                    float pk = __shfl_up_sync(FULLM, key[r], 1);
                    int   pi = __shfl_up_sync(FULLM, idx[r], 1);
                    if (v < key[r]) {
                        if (lane > 0 && v < pk) { key[r] = pk; idx[r] = pi; }
                        else                    { key[r] = v;  idx[r] = vi; }
                    }
                    th[r] = __shfl_sync(FULLM, key[r], 15);
                }
            }
        }
    }

    if (lane < KNN) {
#pragma unroll
        for (int r = 0; r < 2; r++)
            g_idx[(base + q0 + r)*KNN + lane] = base + idx[r];
    }
}

// ---------------------------------------------------------------------------
// Precompute Q[n], P[n]: warp per point, 512 threads (16 points/block) so the
// W1 smem fill is amortized over 2x the points.
// ---------------------------------------------------------------------------
__global__ void __launch_bounds__(512) precomp_kernel(
    const float* __restrict__ verts, const float* __restrict__ feat,
    const float* __restrict__ W1, const float* __restrict__ b1)
{
    __shared__ float sW1[EIN*HID];   // 34.3KB
    int tid = threadIdx.x, lane = tid & 31, w = tid >> 5;
    for (int e = tid; e < EIN*HID; e += 512) sW1[e] = W1[e];
    __syncthreads();

    int p = blockIdx.x * 16 + w;
    float4 f4 = make_float4(0.f,0.f,0.f,0.f);
    if (lane < 8) f4 = *(const float4*)&feat[p*CIN + lane*4];
    float vx = verts[p*3+0], vy = verts[p*3+1], vz = verts[p*3+2];

    int c = lane*4;
    float4 q  = make_float4(0.f,0.f,0.f,0.f);
    float4 pp = *(const float4*)&b1[c];

#pragma unroll
    for (int src = 0; src < 8; src++) {
        float fx = __shfl_sync(FULLM, f4.x, src);
        float fy = __shfl_sync(FULLM, f4.y, src);
        float fz = __shfl_sync(FULLM, f4.z, src);
        float fw = __shfl_sync(FULLM, f4.w, src);
        float fv[4] = {fx, fy, fz, fw};
        int k0 = src*4;
#pragma unroll
        for (int kk = 0; kk < 4; kk++) {
            int k = k0 + kk;
            float4 wa = *(const float4*)&sW1[k*HID + c];          // W1a row k
            float4 wb = *(const float4*)&sW1[(CIN + k)*HID + c];  // W1b row k
            q.x  = fmaf(fv[kk], wa.x, q.x);  q.y  = fmaf(fv[kk], wa.y, q.y);
            q.z  = fmaf(fv[kk], wa.z, q.z);  q.w  = fmaf(fv[kk], wa.w, q.w);
            pp.x = fmaf(fv[kk], wb.x, pp.x); pp.y = fmaf(fv[kk], wb.y, pp.y);
            pp.z = fmaf(fv[kk], wb.z, pp.z); pp.w = fmaf(fv[kk], wb.w, pp.w);
        }
    }
    float vv[3] = {vx, vy, vz};
#pragma unroll
    for (int k = 0; k < 3; k++) {
        float4 wc = *(const float4*)&sW1[(2*CIN + k)*HID + c];
        q.x  = fmaf(vv[k],  wc.x, q.x);  q.y  = fmaf(vv[k],  wc.y, q.y);
        q.z  = fmaf(vv[k],  wc.z, q.z);  q.w  = fmaf(vv[k],  wc.w, q.w);
        pp.x = fmaf(-vv[k], wc.x, pp.x); pp.y = fmaf(-vv[k], wc.y, pp.y);
        pp.z = fmaf(-vv[k], wc.z, pp.z); pp.w = fmaf(-vv[k], wc.w, pp.w);
    }
    *(float4*)&g_q[p*HID + c] = q;
    *(float4*)&g_p[p*HID + c] = pp;
}

// ---------------------------------------------------------------------------
__device__ __forceinline__ float gelu_fast(float x) {
    float z2 = 1.5957691216057308f * fmaf(0.044715f * x * x, x, x);
    float e  = __expf(z2);
    float r  = __fdividef(1.0f, e + 1.0f);
    return x - x * r;
}

// ---------------------------------------------------------------------------
// Edge kernel: warp per point, 512 threads (16 points/block) to halve the
// W2 smem fill traffic. Two neighbors per iteration for reduction ILP.
// ---------------------------------------------------------------------------
__global__ void __launch_bounds__(512) edge_kernel(
    const float* __restrict__ g1, const float* __restrict__ be1,
    const float* __restrict__ W2, const float* __restrict__ b2)
{
    __shared__ float sW2[HID*COUT];   // 32KB
    int tid = threadIdx.x, lane = tid & 31, w = tid >> 5;
    for (int e = tid; e < HID*COUT; e += 512) sW2[e] = W2[e];
    __syncthreads();

    int p = blockIdx.x * 16 + w;
    int myidx = (lane < KNN) ? g_idx[p*KNN + lane] : 0;
    int c = lane * 4;

    float4 P4  = *(const float4*)&g_p[p*HID + c];
    float4 g1v = *(const float4*)&g1[c];
    float4 bev = *(const float4*)&be1[c];

    float4 accG = make_float4(0.f,0.f,0.f,0.f);

    int nb0 = __shfl_sync(FULLM, myidx, 0);
    int nb1 = __shfl_sync(FULLM, myidx, 1);
    float4 qa = __ldg((const float4*)&g_q[nb0*HID + c]);
    float4 qb = __ldg((const float4*)&g_q[nb1*HID + c]);

#pragma unroll
    for (int n = 0; n < KNN; n += 2) {
        float4 h0, h1;
        h0.x = qa.x + P4.x; h0.y = qa.y + P4.y; h0.z = qa.z + P4.z; h0.w = qa.w + P4.w;
        h1.x = qb.x + P4.x; h1.y = qb.y + P4.y; h1.z = qb.z + P4.z; h1.w = qb.w + P4.w;
        if (n + 2 < KNN) {
            int na  = __shfl_sync(FULLM, myidx, n+2);
            int nbx = __shfl_sync(FULLM, myidx, n+3);
            qa = __ldg((const float4*)&g_q[na*HID + c]);
            qb = __ldg((const float4*)&g_q[nbx*HID + c]);
        }
        float s0  = (h0.x + h0.y) + (h0.z + h0.w);
        float s20 = fmaf(h0.x,h0.x, fmaf(h0.y,h0.y, fmaf(h0.z,h0.z, h0.w*h0.w)));
        float s1  = (h1.x + h1.y) + (h1.z + h1.w);
        float s21 = fmaf(h1.x,h1.x, fmaf(h1.y,h1.y, fmaf(h1.z,h1.z, h1.w*h1.w)));
#pragma unroll
        for (int off = 16; off; off >>= 1) {
            s0  += __shfl_xor_sync(FULLM, s0,  off);
            s1  += __shfl_xor_sync(FULLM, s1,  off);
            s20 += __shfl_xor_sync(FULLM, s20, off);
            s21 += __shfl_xor_sync(FULLM, s21, off);
        }
        float mu0  = s0  * (1.f/HID);
        float var0 = s20 * (1.f/HID) - mu0*mu0;
        float rs0  = rsqrtf(var0 + 1e-5f);
        float mu1  = s1  * (1.f/HID);
        float var1 = s21 * (1.f/HID) - mu1*mu1;
        float rs1  = rsqrtf(var1 + 1e-5f);
        accG.x += gelu_fast(fmaf((h0.x - mu0)*rs0, g1v.x, bev.x));
        accG.y += gelu_fast(fmaf((h0.y - mu0)*rs0, g1v.y, bev.y));
        accG.z += gelu_fast(fmaf((h0.z - mu0)*rs0, g1v.z, bev.z));
        accG.w += gelu_fast(fmaf((h0.w - mu0)*rs0, g1v.w, bev.w));
        accG.x += gelu_fast(fmaf((h1.x - mu1)*rs1, g1v.x, bev.x));
        accG.y += gelu_fast(fmaf((h1.y - mu1)*rs1, g1v.y, bev.y));
        accG.z += gelu_fast(fmaf((h1.z - mu1)*rs1, g1v.z, bev.z));
        accG.w += gelu_fast(fmaf((h1.w - mu1)*rs1, g1v.w, bev.w));
    }
    accG.x *= (1.f/KNN); accG.y *= (1.f/KNN);
    accG.z *= (1.f/KNN); accG.w *= (1.f/KNN);

    // fused mid = G @ W2 + b2  (lane handles cols lane, lane+32)
    float m0 = __ldg(&b2[lane]);
    float m1 = __ldg(&b2[lane + 32]);
#pragma unroll
    for (int src = 0; src < 32; src++) {
        float gx = __shfl_sync(FULLM, accG.x, src);
        float gy = __shfl_sync(FULLM, accG.y, src);
        float gz = __shfl_sync(FULLM, accG.z, src);
        float gw = __shfl_sync(FULLM, accG.w, src);
        int k0 = src * 4;
        m0 = fmaf(gx, sW2[(k0+0)*COUT + lane], m0);
        m0 = fmaf(gy, sW2[(k0+1)*COUT + lane], m0);
        m0 = fmaf(gz, sW2[(k0+2)*COUT + lane], m0);
        m0 = fmaf(gw, sW2[(k0+3)*COUT + lane], m0);
        m1 = fmaf(gx, sW2[(k0+0)*COUT + lane + 32], m1);
        m1 = fmaf(gy, sW2[(k0+1)*COUT + lane + 32], m1);
        m1 = fmaf(gz, sW2[(k0+2)*COUT + lane + 32], m1);
        m1 = fmaf(gw, sW2[(k0+3)*COUT + lane + 32], m1);
    }
    g_mid[p*COUT + lane]      = m0;
    g_mid[p*COUT + lane + 32] = m1;
}

// ---------------------------------------------------------------------------
// MLP2 fused: 64 points per block, 82KB smem -> 2 blocks/SM, grid 256.
// ---------------------------------------------------------------------------
#define M2PTS 64
#define SMEM2_FLOATS (COUT*M2PTS + COUT*HID + HID*COUT)  // 20480

__global__ void __launch_bounds__(256, 2) mlp2_kernel(
    const float* __restrict__ Wo1, const float* __restrict__ bo1,
    const float* __restrict__ go,  const float* __restrict__ beo,
    const float* __restrict__ Wo2, const float* __restrict__ bo2,
    float* __restrict__ out)
{
    extern __shared__ float sm[];
    float* sAt  = sm;                       // [64 k][64 rows]
    float* sWo1 = sm + COUT*M2PTS;          // [64 k][128]
    float* sH   = sm;                       // [64 rows][132] aliases sAt+sWo1
    float* sWo2 = sm + COUT*M2PTS + COUT*HID;  // [128 k][64]

    int tid = threadIdx.x;
    int r0  = blockIdx.x * M2PTS;

    for (int e = tid; e < COUT*HID; e += 256) sWo1[e] = Wo1[e];
    for (int e = tid; e < HID*COUT; e += 256) sWo2[e] = Wo2[e];
    for (int e = tid; e < COUT*M2PTS; e += 256) {
        int r = e & (M2PTS-1), k = e >> 6;
        sAt[k*M2PTS + r] = g_mid[(r0 + r)*COUT + k];
    }
    __syncthreads();

    int tx = tid & 15, ty = tid >> 4;

    float acc[4][8];
#pragma unroll
    for (int i = 0; i < 4; i++)
#pragma unroll
        for (int j = 0; j < 8; j++) acc[i][j] = 0.f;

    for (int k = 0; k < COUT; k++) {
        float4 a4 = *(const float4*)&sAt[k*M2PTS + ty*4];
        float4 c0 = *(const float4*)&sWo1[k*HID + tx*8];
        float4 c1 = *(const float4*)&sWo1[k*HID + tx*8 + 4];
        float a[4] = {a4.x,a4.y,a4.z,a4.w};
        float wv[8] = {c0.x,c0.y,c0.z,c0.w,c1.x,c1.y,c1.z,c1.w};
#pragma unroll
        for (int i = 0; i < 4; i++)
#pragma unroll
            for (int j = 0; j < 8; j++)
                acc[i][j] = fmaf(a[i], wv[j], acc[i][j]);
    }

    __syncthreads();

    float b1j[8], gj[8], bej[8];
#pragma unroll
    for (int j = 0; j < 8; j++) {
        int col = tx*8 + j;
        b1j[j] = bo1[col]; gj[j] = go[col]; bej[j] = beo[col];
    }
#pragma unroll
    for (int i = 0; i < 4; i++) {
        float ps = 0.f, ps2 = 0.f;
#pragma unroll
        for (int j = 0; j < 8; j++) {
            float h = acc[i][j] + b1j[j];
            acc[i][j] = h;
            ps += h; ps2 = fmaf(h, h, ps2);
        }
#pragma unroll
        for (int off = 8; off; off >>= 1) {
            ps  += __shfl_xor_sync(FULLM, ps,  off);
            ps2 += __shfl_xor_sync(FULLM, ps2, off);
        }
        float mu  = ps  * (1.f/HID);
        float var = ps2 * (1.f/HID) - mu*mu;
        float rs  = rsqrtf(var + 1e-5f);
        float o[8];
#pragma unroll
        for (int j = 0; j < 8; j++)
            o[j] = gelu_fast(fmaf((acc[i][j] - mu)*rs, gj[j], bej[j]));
        int row = ty*4 + i;
        *(float4*)&sH[row*132 + tx*8]     = make_float4(o[0],o[1],o[2],o[3]);
        *(float4*)&sH[row*132 + tx*8 + 4] = make_float4(o[4],o[5],o[6],o[7]);
    }
    __syncthreads();

    float acc2[4][4];
#pragma unroll
    for (int i = 0; i < 4; i++)
#pragma unroll
        for (int j = 0; j < 4; j++) acc2[i][j] = 0.f;

    for (int k = 0; k < HID; k += 4) {
        float4 w0 = *(const float4*)&sWo2[(k+0)*COUT + tx*4];
        float4 w1 = *(const float4*)&sWo2[(k+1)*COUT + tx*4];
        float4 w2 = *(const float4*)&sWo2[(k+2)*COUT + tx*4];
        float4 w3 = *(const float4*)&sWo2[(k+3)*COUT + tx*4];
#pragma unroll
        for (int i = 0; i < 4; i++) {
            float4 av = *(const float4*)&sH[(ty*4+i)*132 + k];
            acc2[i][0] = fmaf(av.x, w0.x, fmaf(av.y, w1.x, fmaf(av.z, w2.x, fmaf(av.w, w3.x, acc2[i][0]))));
            acc2[i][1] = fmaf(av.x, w0.y, fmaf(av.y, w1.y, fmaf(av.z, w2.y, fmaf(av.w, w3.y, acc2[i][1]))));
            acc2[i][2] = fmaf(av.x, w0.z, fmaf(av.y, w1.z, fmaf(av.z, w2.z, fmaf(av.w, w3.z, acc2[i][2]))));
            acc2[i][3] = fmaf(av.x, w0.w, fmaf(av.y, w1.w, fmaf(av.z, w2.w, fmaf(av.w, w3.w, acc2[i][3]))));
        }
    }

    float b2j[4];
#pragma unroll
    for (int j = 0; j < 4; j++) b2j[j] = bo2[tx*4 + j];
#pragma unroll
    for (int i = 0; i < 4; i++) {
        int row = r0 + ty*4 + i;
#pragma unroll
        for (int j = 0; j < 4; j++)
            out[row*COUT + tx*4 + j] = acc2[i][j] + b2j[j];
    }
}

// ---------------------------------------------------------------------------
extern "C" void kernel_launch(void* const* d_in, const int* in_sizes, int n_in,
                              void* d_out, int out_size) {
    const float* verts = (const float*)d_in[0];
    const float* feat  = (const float*)d_in[1];
    const float* W1    = (const float*)d_in[2];
    const float* b1    = (const float*)d_in[3];
    const float* g1    = (const float*)d_in[4];
    const float* be1   = (const float*)d_in[5];
    const float* W2    = (const float*)d_in[6];
    const float* b2    = (const float*)d_in[7];
    const float* Wo1   = (const float*)d_in[8];
    const float* bo1   = (const float*)d_in[9];
    const float* go    = (const float*)d_in[10];
    const float* beo   = (const float*)d_in[11];
    const float* Wo2   = (const float*)d_in[12];
    const float* bo2   = (const float*)d_in[13];
    float* out = (float*)d_out;

    const int smem2 = SMEM2_FLOATS * 4;   // 81920
    cudaFuncSetAttribute(mlp2_kernel, cudaFuncAttributeMaxDynamicSharedMemorySize, smem2);

    prep_kernel<<<(TOT + 255)/256, 256>>>(verts);
    knn_kernel<<<TOT/16, 256>>>();                         // 2 queries per warp
    precomp_kernel<<<TOT/16, 512>>>(verts, feat, W1, b1);
    edge_kernel<<<TOT/16, 512>>>(g1, be1, W2, b2);
    mlp2_kernel<<<TOT/M2PTS, 256, smem2>>>(Wo1, bo1, go, beo, Wo2, bo2, out);
}